// round 14
// baseline (speedup 1.0000x reference)
#include <cuda_runtime.h>
#include <cuda_bf16.h>
#include <cstdint>
#include <math.h>

// Problem constants
#define BATCH   2
#define SEQ     2048
#define HID     1024
#define HEADS   16
#define DH      64
#define MTOT    (BATCH * SEQ)          // 4096
#define NBH     (BATCH * HEADS)        // 32

// ---------------------------------------------------------------------------
// Scratch (device globals — no allocation allowed)
// ---------------------------------------------------------------------------
#define QKV_ELEMS ((size_t)NBH * SEQ * DH)
__device__ __nv_bfloat16 g_q_h[QKV_ELEMS], g_q_l[QKV_ELEMS];
__device__ __nv_bfloat16 g_k_h[QKV_ELEMS], g_k_l[QKV_ELEMS];
__device__ __nv_bfloat16 g_v_h[QKV_ELEMS], g_v_l[QKV_ELEMS];
__device__ __nv_bfloat16 g_attn_h[(size_t)MTOT * HID];
__device__ __nv_bfloat16 g_attn_l[(size_t)MTOT * HID];
__device__ __nv_bfloat16 g_x_h[(size_t)MTOT * HID];
__device__ __nv_bfloat16 g_x_l[(size_t)MTOT * HID];
__device__ __nv_bfloat16 g_wq_h[(size_t)3 * HID * HID];   // [3072][1024] = W_qkv^T
__device__ __nv_bfloat16 g_wq_l[(size_t)3 * HID * HID];
__device__ __nv_bfloat16 g_wo_h[(size_t)HID * HID];       // [1024][1024] = W_out^T
__device__ __nv_bfloat16 g_wo_l[(size_t)HID * HID];

// ---------------------------------------------------------------------------
// PTX helpers (baseline sm_103 ISA: ldmatrix + mma.sync + cp.async)
// ---------------------------------------------------------------------------
__device__ __forceinline__ uint32_t smem_u32(const void* p) {
    uint32_t a;
    asm("{ .reg .u64 t; cvta.to.shared.u64 t, %1; cvt.u32.u64 %0, t; }" : "=r"(a) : "l"(p));
    return a;
}
#define SWZ(o) ((o) ^ (((o) >> 3) & 0x70))
#define STS128(addr, v) \
    asm volatile("st.shared.v4.b32 [%0], {%1,%2,%3,%4};" \
                 :: "r"(addr), "r"(v.x), "r"(v.y), "r"(v.z), "r"(v.w) : "memory")

#define LDSM_X4(r, addr) \
    asm volatile("ldmatrix.sync.aligned.m8n8.x4.shared.b16 {%0,%1,%2,%3}, [%4];" \
        : "=r"((r)[0]), "=r"((r)[1]), "=r"((r)[2]), "=r"((r)[3]) : "r"(addr))
#define LDSM_X4T(r, addr) \
    asm volatile("ldmatrix.sync.aligned.m8n8.x4.trans.shared.b16 {%0,%1,%2,%3}, [%4];" \
        : "=r"((r)[0]), "=r"((r)[1]), "=r"((r)[2]), "=r"((r)[3]) : "r"(addr))
#define MMA16816(d, a, b) \
    asm volatile("mma.sync.aligned.m16n8k16.row.col.f32.bf16.bf16.f32 " \
        "{%0,%1,%2,%3}, {%4,%5,%6,%7}, {%8,%9}, {%0,%1,%2,%3};" \
        : "+f"((d)[0]), "+f"((d)[1]), "+f"((d)[2]), "+f"((d)[3]) \
        : "r"((a)[0]), "r"((a)[1]), "r"((a)[2]), "r"((a)[3]), \
          "r"((b)[0]), "r"((b)[1]))

#define CP16(dst, src) \
    asm volatile("cp.async.cg.shared.global [%0], [%1], 16;" :: "r"(dst), "l"(src) : "memory")
#define CPCOMMIT() asm volatile("cp.async.commit_group;" ::: "memory")
#define CPWAIT0()  asm volatile("cp.async.wait_group 0;" ::: "memory")

__device__ __forceinline__ uint32_t bf2u(__nv_bfloat16 lo, __nv_bfloat16 hi) {
    union { __nv_bfloat162 b; uint32_t u; } c;
    c.b = __halves2bfloat162(lo, hi);
    return c.u;
}

// ---------------------------------------------------------------------------
// Prep kernels: fp32 -> bf16 hi/lo split (and weight transpose)
// ---------------------------------------------------------------------------
__global__ __launch_bounds__(256) void split_f32(
    const float* __restrict__ s, __nv_bfloat16* __restrict__ hi,
    __nv_bfloat16* __restrict__ lo, int n4)
{
    int i = blockIdx.x * 256 + threadIdx.x;
    if (i >= n4) return;
    float4 v = ((const float4*)s)[i];
    union { __nv_bfloat16 b[4]; uint2 u; } ph, pl;
    float f[4] = {v.x, v.y, v.z, v.w};
#pragma unroll
    for (int j = 0; j < 4; j++) {
        __nv_bfloat16 h = __float2bfloat16(f[j]);
        ph.b[j] = h;
        pl.b[j] = __float2bfloat16(f[j] - __bfloat162float(h));
    }
    ((uint2*)hi)[i] = ph.u;
    ((uint2*)lo)[i] = pl.u;
}

// W[K][N] -> Th/Tl[N][K]  (transpose + split)
__global__ void transpose_split(const float* __restrict__ W,
                                __nv_bfloat16* __restrict__ Th,
                                __nv_bfloat16* __restrict__ Tl, int K, int N)
{
    __shared__ float t[32][33];
    const int k0 = blockIdx.y * 32, n0 = blockIdx.x * 32;
    const int tx = threadIdx.x, ty = threadIdx.y;
    for (int j = ty; j < 32; j += 8)
        t[j][tx] = W[(size_t)(k0 + j) * N + n0 + tx];
    __syncthreads();
    for (int j = ty; j < 32; j += 8) {
        float v = t[tx][j];
        __nv_bfloat16 h = __float2bfloat16(v);
        Th[(size_t)(n0 + j) * K + k0 + tx] = h;
        Tl[(size_t)(n0 + j) * K + k0 + tx] = __float2bfloat16(v - __bfloat162float(h));
    }
}

// ---------------------------------------------------------------------------
// mma.sync GEMM, bf16 hi/lo split (3 passes), fp32 accumulate.
// 512 threads = 16 warps (4M x 4N), 32x32 warp tile -> 4 warps/SMSP.
// cp.async 2-stage pipelined mainloop (K-chunk 64).
// C[M,N] = A[M,K] @ B[N,K]^T + bias[N]
// mode 0: plain write to C.  mode 1: write Q/K/V bf16 hi/lo (Q pre-scaled).
// ---------------------------------------------------------------------------
#define GT_SMEM (128 * 1024 + 1024)

__global__ __launch_bounds__(512, 1) void gemm_tc(
    const __nv_bfloat16* __restrict__ Ah, const __nv_bfloat16* __restrict__ Al,
    const __nv_bfloat16* __restrict__ Bh, const __nv_bfloat16* __restrict__ Bl,
    const float* __restrict__ bias, float* __restrict__ C,
    int M, int N, int K, int mode)
{
    extern __shared__ char smraw[];
    const uint32_t tile = (smem_u32(smraw) + 1023u) & ~1023u;
    // stage s at tile + s*65536: A_h 0 | A_l 16K | B_h 32K | B_l 48K

    const int tid  = threadIdx.x;
    const int wid  = tid >> 5, lane = tid & 31;
    const int wm   = wid & 3, wn = wid >> 2;        // 4 x 4 warp grid
    const int bm   = blockIdx.y << 7, bn = blockIdx.x << 7;

    uint32_t a_base[2], b_base[2];
#pragma unroll
    for (int mi = 0; mi < 2; mi++) {
        const int rowA = wm * 32 + mi * 16 + (lane & 15);
        a_base[mi] = (uint32_t)rowA * 128 + (((uint32_t)lane >> 4) << 4);
    }
    const int brow = (lane & 7) + ((lane >> 4) << 3);
    const uint32_t bchunk = (((uint32_t)lane >> 3) & 1) << 4;
#pragma unroll
    for (int nf = 0; nf < 2; nf++) {
        const int rowB = wn * 32 + nf * 16 + brow;
        b_base[nf] = (uint32_t)rowB * 128 + bchunk;
    }

    float d[2][4][4];
#pragma unroll
    for (int mi = 0; mi < 2; mi++)
#pragma unroll
        for (int ni = 0; ni < 4; ni++)
#pragma unroll
            for (int k = 0; k < 4; k++) d[mi][ni][k] = 0.f;

    // ---- prologue: issue chunk 0 into stage 0 ----
    {
        const uint32_t st = tile;
#pragma unroll
        for (int i = 0; i < 2; i++) {
            const int idx = tid + (i << 9);        // 0..1023
            const int r = idx >> 3, c = idx & 7;
            const uint32_t so = SWZ((uint32_t)r * 128 + (uint32_t)c * 16);
            const size_t gA = (size_t)(bm + r) * K + c * 8;
            const size_t gB = (size_t)(bn + r) * K + c * 8;
            CP16(st + so,         Ah + gA);
            CP16(st + 16384 + so, Al + gA);
            CP16(st + 32768 + so, Bh + gB);
            CP16(st + 49152 + so, Bl + gB);
        }
        CPCOMMIT();
    }

    int stg = 0;
    for (int kc = 0; kc < K; kc += 64, stg ^= 1) {
        CPWAIT0();
        __syncthreads();

        if (kc + 64 < K) {
            const uint32_t st = tile + (uint32_t)(stg ^ 1) * 65536u;
#pragma unroll
            for (int i = 0; i < 2; i++) {
                const int idx = tid + (i << 9);
                const int r = idx >> 3, c = idx & 7;
                const uint32_t so = SWZ((uint32_t)r * 128 + (uint32_t)c * 16);
                const size_t gA = (size_t)(bm + r) * K + kc + 64 + c * 8;
                const size_t gB = (size_t)(bn + r) * K + kc + 64 + c * 8;
                CP16(st + so,         Ah + gA);
                CP16(st + 16384 + so, Al + gA);
                CP16(st + 32768 + so, Bh + gB);
                CP16(st + 49152 + so, Bl + gB);
            }
            CPCOMMIT();
        }

        const uint32_t sA_h = tile + (uint32_t)stg * 65536u;
        const uint32_t sA_l = sA_h + 16384, sB_h = sA_h + 32768, sB_l = sA_h + 49152;

#pragma unroll
        for (int ks = 0; ks < 4; ks++) {
            const uint32_t kb = (uint32_t)ks << 5;
            uint32_t fAh[2][4], fAl[2][4], fBh[2][4], fBl[2][4];
#pragma unroll
            for (int mi = 0; mi < 2; mi++) {
                LDSM_X4(fAh[mi], sA_h + SWZ(a_base[mi] + kb));
                LDSM_X4(fAl[mi], sA_l + SWZ(a_base[mi] + kb));
            }
#pragma unroll
            for (int nf = 0; nf < 2; nf++) {
                LDSM_X4(fBh[nf], sB_h + SWZ(b_base[nf] + kb));
                LDSM_X4(fBl[nf], sB_l + SWZ(b_base[nf] + kb));
            }
#pragma unroll
            for (int pass = 0; pass < 3; pass++)
#pragma unroll
                for (int mi = 0; mi < 2; mi++)
#pragma unroll
                    for (int ni = 0; ni < 4; ni++) {
                        const uint32_t* a = (pass == 2) ? fAl[mi] : fAh[mi];
                        const uint32_t* b = (pass == 1) ? fBl[ni >> 1] : fBh[ni >> 1];
                        MMA16816(d[mi][ni], a, &b[(ni & 1) * 2]);
                    }
        }
    }

    // ---- epilogue ----
    const int q = lane >> 2;
    const int cpair = (lane & 3) << 1;
#pragma unroll
    for (int ni = 0; ni < 4; ni++) {
        const int n = bn + wn * 32 + ni * 8 + cpair;
        const float2 bs = *(const float2*)(bias + n);
#pragma unroll
        for (int mi = 0; mi < 2; mi++) {
#pragma unroll
            for (int hh = 0; hh < 2; hh++) {
                const int m = bm + wm * 32 + mi * 16 + q + hh * 8;
                float2 v;
                v.x = d[mi][ni][hh * 2 + 0] + bs.x;
                v.y = d[mi][ni][hh * 2 + 1] + bs.y;
                if (mode == 1) {
                    const int cc = n >> 10, hd = (n >> 6) & 15, dd = n & 63;
                    const int bb = m >> 11, ss = m & 2047;
                    const float sc = (cc == 0) ? 0.125f : 1.0f;
                    const float vx = v.x * sc, vy = v.y * sc;
                    const __nv_bfloat16 hx = __float2bfloat16(vx);
                    const __nv_bfloat16 hy = __float2bfloat16(vy);
                    const __nv_bfloat16 lx = __float2bfloat16(vx - __bfloat162float(hx));
                    const __nv_bfloat16 ly = __float2bfloat16(vy - __bfloat162float(hy));
                    const size_t off = ((size_t)(bb * HEADS + hd) * SEQ + ss) * DH + dd;
                    __nv_bfloat16* dh = (cc == 0) ? g_q_h : (cc == 1) ? g_k_h : g_v_h;
                    __nv_bfloat16* dl = (cc == 0) ? g_q_l : (cc == 1) ? g_k_l : g_v_l;
                    *(uint32_t*)(dh + off) = bf2u(hx, hy);
                    *(uint32_t*)(dl + off) = bf2u(lx, ly);
                } else {
                    *(float2*)(C + (size_t)m * N + n) = v;
                }
            }
        }
    }
}

// ---------------------------------------------------------------------------
// Tensor-core flash attention: 256 threads / 8 warps, 16 q-rows per warp,
// 128 q-rows per CTA, 2 CTAs/SM (96KB smem) -> 16 warps/SM = 4/SMSP.
// 64-key tiles, cp.async double-buffered. QK^T and PV 3-pass bf16 hi/lo.
// Register diet: ql reloaded from smem per k-step; K/V frags loaded per-g.
// ---------------------------------------------------------------------------
#define AT_SMEM (96 * 1024 + 1024)

__global__ __launch_bounds__(256, 2) void attn_mma()
{
    extern __shared__ char smraw[];
    const uint32_t base = (smem_u32(smraw) + 1023u) & ~1023u;
    const uint32_t sQh = base, sQl = base + 16384;
    const uint32_t sStage = base + 32768;  // + s*32768: Kh 0 | Kl 8K | Vh 16K | Vl 24K

    const int tid = threadIdx.x, lane = tid & 31, wid = tid >> 5;
    const int bh = blockIdx.y;
    const int q0 = blockIdx.x << 7;
    const size_t hbase = (size_t)bh * (SEQ * DH);

    // ---- prologue: cp.async key-tile 0 ----
    {
        const uint32_t st = sStage;
#pragma unroll
        for (int j = 0; j < 2; j++) {
            const int idx = tid + (j << 8);        // 0..511
            const int r = idx >> 3, c = idx & 7;
            const uint32_t so = SWZ((uint32_t)r * 128 + (uint32_t)c * 16);
            const size_t g = hbase + (size_t)r * DH + c * 8;
            CP16(st + so,         g_k_h + g);
            CP16(st + 8192 + so,  g_k_l + g);
            CP16(st + 16384 + so, g_v_h + g);
            CP16(st + 24576 + so, g_v_l + g);
        }
        CPCOMMIT();
    }
    // stage Q (one-time)
    for (int i = tid; i < 1024; i += 256) {
        const int r = i >> 3, c = i & 7;
        const uint32_t so = SWZ((uint32_t)r * 128 + (uint32_t)c * 16);
        const size_t g = hbase + (size_t)(q0 + r) * DH + c * 8;
        uint4 v;
        v = *(const uint4*)(g_q_h + g); STS128(sQh + so, v);
        v = *(const uint4*)(g_q_l + g); STS128(sQl + so, v);
    }
    __syncthreads();

    // Persistent Q hi fragments only (lo reloaded per k-step: register diet)
    const uint32_t qoff = (uint32_t)(wid * 16 + (lane & 15)) * 128 + ((lane >> 4) << 4);
    uint32_t qh[4][4];
#pragma unroll
    for (int ks = 0; ks < 4; ks++)
        LDSM_X4(qh[ks], sQh + SWZ(qoff + ks * 32));

    float O[8][4];
#pragma unroll
    for (int nt = 0; nt < 8; nt++)
#pragma unroll
        for (int e = 0; e < 4; e++) O[nt][e] = 0.f;
    float m0 = -3.0e38f, m1 = -3.0e38f, l0 = 0.f, l1 = 0.f;

    const int krow = (lane & 7) + ((lane >> 4) << 3);
    const uint32_t kchunk = (((uint32_t)lane >> 3) & 1) << 4;
    const int vrow_l = lane & 15;
    const uint32_t vchunk = ((uint32_t)lane >> 4) << 4;

    for (int kt = 0; kt < SEQ / 64; kt++) {
        CPWAIT0();
        __syncthreads();

        if (kt + 1 < SEQ / 64) {
            const size_t rb = hbase + (size_t)((kt + 1) << 6) * DH;
            const uint32_t st = sStage + ((kt + 1) & 1) * 32768;
#pragma unroll
            for (int j = 0; j < 2; j++) {
                const int idx = tid + (j << 8);
                const int r = idx >> 3, c = idx & 7;
                const uint32_t so = SWZ((uint32_t)r * 128 + (uint32_t)c * 16);
                const size_t g = rb + (size_t)r * DH + c * 8;
                CP16(st + so,         g_k_h + g);
                CP16(st + 8192 + so,  g_k_l + g);
                CP16(st + 16384 + so, g_v_h + g);
                CP16(st + 24576 + so, g_v_l + g);
            }
            CPCOMMIT();
        }

        const uint32_t stK_h = sStage + (kt & 1) * 32768;
        const uint32_t stK_l = stK_h + 8192;
        const uint32_t stV_h = stK_h + 16384;
        const uint32_t stV_l = stK_h + 24576;

        // ---- S = Qhi*Khi + Qhi*Klo + Qlo*Khi ----
        float S[8][4];
#pragma unroll
        for (int nt = 0; nt < 8; nt++)
#pragma unroll
            for (int e = 0; e < 4; e++) S[nt][e] = 0.f;

#pragma unroll
        for (int ks = 0; ks < 4; ks++) {
            uint32_t qlv[4];
            LDSM_X4(qlv, sQl + SWZ(qoff + ks * 32));
#pragma unroll
            for (int g = 0; g < 4; g++) {
                uint32_t kbh[4], kbl[4];
                const uint32_t off = SWZ((uint32_t)(g * 16 + krow) * 128 + (ks << 5) + kchunk);
                LDSM_X4(kbh, stK_h + off);
                LDSM_X4(kbl, stK_l + off);
                MMA16816(S[2 * g],     qh[ks], &kbh[0]);
                MMA16816(S[2 * g + 1], qh[ks], &kbh[2]);
                MMA16816(S[2 * g],     qh[ks], &kbl[0]);
                MMA16816(S[2 * g + 1], qh[ks], &kbl[2]);
                MMA16816(S[2 * g],     qlv,    &kbh[0]);
                MMA16816(S[2 * g + 1], qlv,    &kbh[2]);
            }
        }

        // ---- online softmax (rows: lane>>2 and +8; quad = lanes xor 1,2) ----
        float rx0 = -3.0e38f, rx1 = -3.0e38f;
#pragma unroll
        for (int nt = 0; nt < 8; nt++) {
            rx0 = fmaxf(rx0, fmaxf(S[nt][0], S[nt][1]));
            rx1 = fmaxf(rx1, fmaxf(S[nt][2], S[nt][3]));
        }
        rx0 = fmaxf(rx0, __shfl_xor_sync(0xffffffffu, rx0, 1));
        rx0 = fmaxf(rx0, __shfl_xor_sync(0xffffffffu, rx0, 2));
        rx1 = fmaxf(rx1, __shfl_xor_sync(0xffffffffu, rx1, 1));
        rx1 = fmaxf(rx1, __shfl_xor_sync(0xffffffffu, rx1, 2));
        const float mn0 = fmaxf(m0, rx0), mn1 = fmaxf(m1, rx1);
        const float a0 = __expf(m0 - mn0), a1 = __expf(m1 - mn1);
        float s0 = 0.f, s1 = 0.f;
#pragma unroll
        for (int nt = 0; nt < 8; nt++) {
            S[nt][0] = __expf(S[nt][0] - mn0);
            S[nt][1] = __expf(S[nt][1] - mn0);
            S[nt][2] = __expf(S[nt][2] - mn1);
            S[nt][3] = __expf(S[nt][3] - mn1);
            s0 += S[nt][0] + S[nt][1];
            s1 += S[nt][2] + S[nt][3];
        }
        s0 += __shfl_xor_sync(0xffffffffu, s0, 1);
        s0 += __shfl_xor_sync(0xffffffffu, s0, 2);
        s1 += __shfl_xor_sync(0xffffffffu, s1, 1);
        s1 += __shfl_xor_sync(0xffffffffu, s1, 2);
        l0 = l0 * a0 + s0; l1 = l1 * a1 + s1;
        m0 = mn0; m1 = mn1;
#pragma unroll
        for (int nt = 0; nt < 8; nt++) {
            O[nt][0] *= a0; O[nt][1] *= a0;
            O[nt][2] *= a1; O[nt][3] *= a1;
        }

        // ---- PV: O += Ph*Vh + Pl*Vh + Ph*Vl (V^T via ldmatrix.trans) ----
#pragma unroll
        for (int c = 0; c < 4; c++) {
            uint32_t ph[4], pl[4];
#pragma unroll
            for (int j = 0; j < 4; j++) {
                const int nt = 2 * c + (j >> 1);
                const int e0 = (j & 1) * 2;
                const float p0 = S[nt][e0], p1 = S[nt][e0 + 1];
                const __nv_bfloat16 b0 = __float2bfloat16(p0);
                const __nv_bfloat16 b1 = __float2bfloat16(p1);
                ph[j] = bf2u(b0, b1);
                pl[j] = bf2u(__float2bfloat16(p0 - __bfloat162float(b0)),
                             __float2bfloat16(p1 - __bfloat162float(b1)));
            }
#pragma unroll
            for (int g = 0; g < 4; g++) {
                uint32_t vbh[4], vbl[4];
                const uint32_t off =
                    SWZ((uint32_t)(c * 16 + vrow_l) * 128 + ((uint32_t)g << 5) + vchunk);
                LDSM_X4T(vbh, stV_h + off);
                LDSM_X4T(vbl, stV_l + off);
                MMA16816(O[2 * g],     ph, &vbh[0]);
                MMA16816(O[2 * g + 1], ph, &vbh[2]);
                MMA16816(O[2 * g],     pl, &vbh[0]);
                MMA16816(O[2 * g + 1], pl, &vbh[2]);
                MMA16816(O[2 * g],     ph, &vbl[0]);
                MMA16816(O[2 * g + 1], ph, &vbl[2]);
            }
        }
    }

    // ---- finalize: O/l -> bf16 hi/lo -> g_attn [b][s][h*64+d] ----
    const float inv0 = 1.0f / l0, inv1 = 1.0f / l1;
    const int b_ = bh >> 4, h_ = bh & 15;
    const int row0 = q0 + wid * 16 + (lane >> 2);
#pragma unroll
    for (int nt = 0; nt < 8; nt++) {
        const int dcol = nt * 8 + ((lane & 3) << 1);
#pragma unroll
        for (int hh = 0; hh < 2; hh++) {
            const int row = row0 + hh * 8;
            const float inv = hh ? inv1 : inv0;
            const float v0 = O[nt][hh * 2 + 0] * inv;
            const float v1 = O[nt][hh * 2 + 1] * inv;
            const __nv_bfloat16 h0 = __float2bfloat16(v0);
            const __nv_bfloat16 h1 = __float2bfloat16(v1);
            const size_t off = ((size_t)b_ * SEQ + row) * HID + h_ * DH + dcol;
            *(uint32_t*)(g_attn_h + off) = bf2u(h0, h1);
            *(uint32_t*)(g_attn_l + off) =
                bf2u(__float2bfloat16(v0 - __bfloat162float(h0)),
                     __float2bfloat16(v1 - __bfloat162float(h1)));
        }
    }
}

// ---------------------------------------------------------------------------
extern "C" void kernel_launch(void* const* d_in, const int* in_sizes, int n_in,
                              void* d_out, int out_size)
{
    const float* x    = (const float*)d_in[0];
    const float* Wqkv = (const float*)d_in[1];
    const float* bqkv = (const float*)d_in[2];
    const float* Wout = (const float*)d_in[3];
    const float* bout = (const float*)d_in[4];
    float* out = (float*)d_out;

    cudaFuncSetAttribute(gemm_tc,
                         cudaFuncAttributeMaxDynamicSharedMemorySize, GT_SMEM);
    cudaFuncSetAttribute(attn_mma,
                         cudaFuncAttributeMaxDynamicSharedMemorySize, AT_SMEM);

    __nv_bfloat16 *xh, *xl, *wqh, *wql, *woh, *wol, *ath, *atl;
    cudaGetSymbolAddress((void**)&xh,  g_x_h);
    cudaGetSymbolAddress((void**)&xl,  g_x_l);
    cudaGetSymbolAddress((void**)&wqh, g_wq_h);
    cudaGetSymbolAddress((void**)&wql, g_wq_l);
    cudaGetSymbolAddress((void**)&woh, g_wo_h);
    cudaGetSymbolAddress((void**)&wol, g_wo_l);
    cudaGetSymbolAddress((void**)&ath, g_attn_h);
    cudaGetSymbolAddress((void**)&atl, g_attn_l);

    // 0) prep: split x; transpose+split weights
    split_f32<<<(MTOT * HID / 4 + 255) / 256, 256>>>(x, xh, xl, MTOT * HID / 4);
    transpose_split<<<dim3(3 * HID / 32, HID / 32), dim3(32, 8)>>>(Wqkv, wqh, wql, HID, 3 * HID);
    transpose_split<<<dim3(HID / 32, HID / 32), dim3(32, 8)>>>(Wout, woh, wol, HID, HID);

    // 1) QKV projection -> Q/K/V bf16 hi/lo (Q pre-scaled by 1/8)
    gemm_tc<<<dim3(3 * HID / 128, MTOT / 128), 512, GT_SMEM>>>(
        xh, xl, wqh, wql, bqkv, nullptr, MTOT, 3 * HID, HID, 1);

    // 2) Tensor-core flash attention -> g_attn_h/l
    attn_mma<<<dim3(SEQ / 128, NBH), 256, AT_SMEM>>>();

    // 3) Output projection + bias -> out
    gemm_tc<<<dim3(HID / 128, MTOT / 128), 512, GT_SMEM>>>(
        ath, atl, woh, wol, bout, out, MTOT, HID, HID, 0);
}

// round 15
// speedup vs baseline: 1.1742x; 1.1742x over previous
#include <cuda_runtime.h>
#include <cuda_bf16.h>
#include <cuda_fp16.h>
#include <cstdint>
#include <math.h>

// Problem constants
#define BATCH   2
#define SEQ     2048
#define HID     1024
#define HEADS   16
#define DH      64
#define MTOT    (BATCH * SEQ)          // 4096
#define NBH     (BATCH * HEADS)        // 32

// ---------------------------------------------------------------------------
// Scratch (device globals — no allocation allowed)
// ---------------------------------------------------------------------------
#define QKV_ELEMS ((size_t)NBH * SEQ * DH)
__device__ __nv_bfloat16 g_q_h[QKV_ELEMS], g_q_l[QKV_ELEMS];
__device__ __nv_bfloat16 g_k_h[QKV_ELEMS], g_k_l[QKV_ELEMS];
__device__ __nv_bfloat16 g_v_h[QKV_ELEMS], g_v_l[QKV_ELEMS];
__device__ __half g_attn_h[(size_t)MTOT * HID];
__device__ __half g_attn_l[(size_t)MTOT * HID];
__device__ __half g_x_h[(size_t)MTOT * HID];
__device__ __half g_x_l[(size_t)MTOT * HID];
__device__ __half g_wq_h[(size_t)3 * HID * HID];   // [3072][1024] = fp16(W_qkv^T)
__device__ __half g_wo_h[(size_t)HID * HID];       // [1024][1024] = fp16(W_out^T)

// ---------------------------------------------------------------------------
// PTX helpers (baseline sm_103 ISA: ldmatrix + mma.sync + cp.async)
// ---------------------------------------------------------------------------
__device__ __forceinline__ uint32_t smem_u32(const void* p) {
    uint32_t a;
    asm("{ .reg .u64 t; cvta.to.shared.u64 t, %1; cvt.u32.u64 %0, t; }" : "=r"(a) : "l"(p));
    return a;
}
#define SWZ(o) ((o) ^ (((o) >> 3) & 0x70))
#define STS128(addr, v) \
    asm volatile("st.shared.v4.b32 [%0], {%1,%2,%3,%4};" \
                 :: "r"(addr), "r"(v.x), "r"(v.y), "r"(v.z), "r"(v.w) : "memory")

#define LDSM_X4(r, addr) \
    asm volatile("ldmatrix.sync.aligned.m8n8.x4.shared.b16 {%0,%1,%2,%3}, [%4];" \
        : "=r"((r)[0]), "=r"((r)[1]), "=r"((r)[2]), "=r"((r)[3]) : "r"(addr))
#define LDSM_X4T(r, addr) \
    asm volatile("ldmatrix.sync.aligned.m8n8.x4.trans.shared.b16 {%0,%1,%2,%3}, [%4];" \
        : "=r"((r)[0]), "=r"((r)[1]), "=r"((r)[2]), "=r"((r)[3]) : "r"(addr))
#define LDSM_X2(r, addr) \
    asm volatile("ldmatrix.sync.aligned.m8n8.x2.shared.b16 {%0,%1}, [%2];" \
        : "=r"((r)[0]), "=r"((r)[1]) : "r"(addr))
// bf16 mma (attention)
#define MMA16816(d, a, b) \
    asm volatile("mma.sync.aligned.m16n8k16.row.col.f32.bf16.bf16.f32 " \
        "{%0,%1,%2,%3}, {%4,%5,%6,%7}, {%8,%9}, {%0,%1,%2,%3};" \
        : "+f"((d)[0]), "+f"((d)[1]), "+f"((d)[2]), "+f"((d)[3]) \
        : "r"((a)[0]), "r"((a)[1]), "r"((a)[2]), "r"((a)[3]), \
          "r"((b)[0]), "r"((b)[1]))
// fp16 mma (projection GEMMs)
#define MMAF16(d, a, b) \
    asm volatile("mma.sync.aligned.m16n8k16.row.col.f32.f16.f16.f32 " \
        "{%0,%1,%2,%3}, {%4,%5,%6,%7}, {%8,%9}, {%0,%1,%2,%3};" \
        : "+f"((d)[0]), "+f"((d)[1]), "+f"((d)[2]), "+f"((d)[3]) \
        : "r"((a)[0]), "r"((a)[1]), "r"((a)[2]), "r"((a)[3]), \
          "r"((b)[0]), "r"((b)[1]))

#define CP16(dst, src) \
    asm volatile("cp.async.cg.shared.global [%0], [%1], 16;" :: "r"(dst), "l"(src) : "memory")
#define CPCOMMIT() asm volatile("cp.async.commit_group;" ::: "memory")
#define CPWAIT0()  asm volatile("cp.async.wait_group 0;" ::: "memory")

__device__ __forceinline__ uint32_t bf2u(__nv_bfloat16 lo, __nv_bfloat16 hi) {
    union { __nv_bfloat162 b; uint32_t u; } c;
    c.b = __halves2bfloat162(lo, hi);
    return c.u;
}
__device__ __forceinline__ uint32_t h2u(__half lo, __half hi) {
    union { __half2 h; uint32_t u; } c;
    c.h = __halves2half2(lo, hi);
    return c.u;
}

// ---------------------------------------------------------------------------
// Prep kernels: fp32 -> fp16 hi/lo split; W[K][N] -> fp16(W^T)[N][K]
// ---------------------------------------------------------------------------
__global__ __launch_bounds__(256) void split_f16(
    const float* __restrict__ s, __half* __restrict__ hi,
    __half* __restrict__ lo, int n4)
{
    int i = blockIdx.x * 256 + threadIdx.x;
    if (i >= n4) return;
    float4 v = ((const float4*)s)[i];
    union { __half b[4]; uint2 u; } ph, pl;
    float f[4] = {v.x, v.y, v.z, v.w};
#pragma unroll
    for (int j = 0; j < 4; j++) {
        __half h = __float2half(f[j]);
        ph.b[j] = h;
        pl.b[j] = __float2half(f[j] - __half2float(h));
    }
    ((uint2*)hi)[i] = ph.u;
    ((uint2*)lo)[i] = pl.u;
}

__global__ void transpose_h(const float* __restrict__ W,
                            __half* __restrict__ Th, int K, int N)
{
    __shared__ float t[32][33];
    const int k0 = blockIdx.y * 32, n0 = blockIdx.x * 32;
    const int tx = threadIdx.x, ty = threadIdx.y;
    for (int j = ty; j < 32; j += 8)
        t[j][tx] = W[(size_t)(k0 + j) * N + n0 + tx];
    __syncthreads();
    for (int j = ty; j < 32; j += 8)
        Th[(size_t)(n0 + j) * K + k0 + tx] = __float2half(t[tx][j]);
}

// ---------------------------------------------------------------------------
// mma.sync GEMM, fp16 2-pass (A 22-bit via hi/lo, W 11-bit), fp32 accumulate.
// cp.async 2-stage pipelined mainloop (K-chunk 64, 48KB/stage).
// C[M,N] = A[M,K] @ B[N,K]^T + bias[N]
// mode 0: plain f32 write to C.  mode 1: write Q/K/V bf16 hi/lo (Q pre-scaled).
// ---------------------------------------------------------------------------
#define GT_SMEM (2 * 49152 + 1024)

__global__ __launch_bounds__(256, 1) void gemm_tc(
    const __half* __restrict__ Ah, const __half* __restrict__ Al,
    const __half* __restrict__ Bh,
    const float* __restrict__ bias, float* __restrict__ C,
    int M, int N, int K, int mode)
{
    extern __shared__ char smraw[];
    const uint32_t tile = (smem_u32(smraw) + 1023u) & ~1023u;
    // stage s at tile + s*49152: A_h 0 | A_l 16K | B_h 32K

    const int tid  = threadIdx.x;
    const int wid  = tid >> 5, lane = tid & 31;
    const int wm   = wid & 1, wn = wid >> 1;        // 2 x 4 warp grid
    const int bm   = blockIdx.y << 7, bn = blockIdx.x << 7;

    uint32_t a_base[4], b_base[4];
#pragma unroll
    for (int mi = 0; mi < 4; mi++) {
        const int rowA = wm * 64 + mi * 16 + (lane & 15);
        a_base[mi] = (uint32_t)rowA * 128 + (((uint32_t)lane >> 4) << 4);
    }
    const int l15 = lane & 15;
#pragma unroll
    for (int ni = 0; ni < 4; ni++) {
        const int rowB = wn * 32 + ni * 8 + (l15 & 7);
        b_base[ni] = (uint32_t)rowB * 128 + (((uint32_t)l15 >> 3) << 4);
    }

    float d[4][4][4];
#pragma unroll
    for (int mi = 0; mi < 4; mi++)
#pragma unroll
        for (int ni = 0; ni < 4; ni++)
#pragma unroll
            for (int k = 0; k < 4; k++) d[mi][ni][k] = 0.f;

    // ---- prologue: issue chunk 0 into stage 0 ----
    {
        const uint32_t st = tile;
#pragma unroll
        for (int i = 0; i < 4; i++) {
            const int idx = tid + (i << 8);
            const int r = idx >> 3, c = idx & 7;
            const uint32_t so = SWZ((uint32_t)r * 128 + (uint32_t)c * 16);
            const size_t gA = (size_t)(bm + r) * K + c * 8;
            const size_t gB = (size_t)(bn + r) * K + c * 8;
            CP16(st + so,         Ah + gA);
            CP16(st + 16384 + so, Al + gA);
            CP16(st + 32768 + so, Bh + gB);
        }
        CPCOMMIT();
    }

    int stg = 0;
    for (int kc = 0; kc < K; kc += 64, stg ^= 1) {
        CPWAIT0();
        __syncthreads();

        if (kc + 64 < K) {
            const uint32_t st = tile + (uint32_t)(stg ^ 1) * 49152u;
#pragma unroll
            for (int i = 0; i < 4; i++) {
                const int idx = tid + (i << 8);
                const int r = idx >> 3, c = idx & 7;
                const uint32_t so = SWZ((uint32_t)r * 128 + (uint32_t)c * 16);
                const size_t gA = (size_t)(bm + r) * K + kc + 64 + c * 8;
                const size_t gB = (size_t)(bn + r) * K + kc + 64 + c * 8;
                CP16(st + so,         Ah + gA);
                CP16(st + 16384 + so, Al + gA);
                CP16(st + 32768 + so, Bh + gB);
            }
            CPCOMMIT();
        }

        const uint32_t sA_h = tile + (uint32_t)stg * 49152u;
        const uint32_t sA_l = sA_h + 16384, sB_h = sA_h + 32768;

#pragma unroll
        for (int ks = 0; ks < 4; ks++) {
            const uint32_t kb = (uint32_t)ks << 5;
            uint32_t fAh[4][4], fAl[4][4], fBh[4][2];
#pragma unroll
            for (int mi = 0; mi < 4; mi++) {
                LDSM_X4(fAh[mi], sA_h + SWZ(a_base[mi] + kb));
                LDSM_X4(fAl[mi], sA_l + SWZ(a_base[mi] + kb));
            }
#pragma unroll
            for (int ni = 0; ni < 4; ni++)
                LDSM_X2(fBh[ni], sB_h + SWZ(b_base[ni] + kb));
            // 2 passes: Ah*Bh + Al*Bh  (pass-major, same-acc spacing 16)
#pragma unroll
            for (int pass = 0; pass < 2; pass++)
#pragma unroll
                for (int mi = 0; mi < 4; mi++)
#pragma unroll
                    for (int ni = 0; ni < 4; ni++) {
                        const uint32_t* a = (pass == 0) ? fAh[mi] : fAl[mi];
                        MMAF16(d[mi][ni], a, fBh[ni]);
                    }
        }
    }

    // ---- epilogue ----
    const int q = lane >> 2;
    const int cpair = (lane & 3) << 1;
#pragma unroll
    for (int ni = 0; ni < 4; ni++) {
        const int n = bn + wn * 32 + ni * 8 + cpair;
        const float2 bs = *(const float2*)(bias + n);
#pragma unroll
        for (int mi = 0; mi < 4; mi++) {
#pragma unroll
            for (int hh = 0; hh < 2; hh++) {
                const int m = bm + wm * 64 + mi * 16 + q + hh * 8;
                float2 v;
                v.x = d[mi][ni][hh * 2 + 0] + bs.x;
                v.y = d[mi][ni][hh * 2 + 1] + bs.y;
                if (mode == 1) {
                    const int cc = n >> 10, hd = (n >> 6) & 15, dd = n & 63;
                    const int bb = m >> 11, ss = m & 2047;
                    const float sc = (cc == 0) ? 0.125f : 1.0f;
                    const float vx = v.x * sc, vy = v.y * sc;
                    const __nv_bfloat16 hx = __float2bfloat16(vx);
                    const __nv_bfloat16 hy = __float2bfloat16(vy);
                    const __nv_bfloat16 lx = __float2bfloat16(vx - __bfloat162float(hx));
                    const __nv_bfloat16 ly = __float2bfloat16(vy - __bfloat162float(hy));
                    const size_t off = ((size_t)(bb * HEADS + hd) * SEQ + ss) * DH + dd;
                    __nv_bfloat16* dh = (cc == 0) ? g_q_h : (cc == 1) ? g_k_h : g_v_h;
                    __nv_bfloat16* dl = (cc == 0) ? g_q_l : (cc == 1) ? g_k_l : g_v_l;
                    *(uint32_t*)(dh + off) = bf2u(hx, hy);
                    *(uint32_t*)(dl + off) = bf2u(lx, ly);
                } else {
                    *(float2*)(C + (size_t)m * N + n) = v;
                }
            }
        }
    }
}

// ---------------------------------------------------------------------------
// Tensor-core flash attention (R13 config, unchanged math): 128 threads /
// 4 warps, 128 q-rows per CTA, 2 CTAs/SM. 64-key tiles, cp.async
// double-buffered. QK^T and PV 3-pass bf16 hi/lo split, pass-major.
// Finalize now emits fp16 hi/lo for the 2-pass output projection.
// ---------------------------------------------------------------------------
#define AT_SMEM (96 * 1024 + 1024)

__global__ __launch_bounds__(128, 2) void attn_mma()
{
    extern __shared__ char smraw[];
    const uint32_t base = (smem_u32(smraw) + 1023u) & ~1023u;
    const uint32_t sQh = base, sQl = base + 16384;
    const uint32_t sStage = base + 32768;  // + s*32768: Kh 0 | Kl 8K | Vh 16K | Vl 24K

    const int tid = threadIdx.x, lane = tid & 31, wid = tid >> 5;
    const int bh = blockIdx.y;
    const int q0 = blockIdx.x << 7;
    const size_t hbase = (size_t)bh * (SEQ * DH);

    // ---- prologue: cp.async key-tile 0 ----
    {
        const uint32_t st = sStage;
#pragma unroll
        for (int j = 0; j < 4; j++) {
            const int idx = tid + (j << 7);        // 0..511
            const int r = idx >> 3, c = idx & 7;
            const uint32_t so = SWZ((uint32_t)r * 128 + (uint32_t)c * 16);
            const size_t g = hbase + (size_t)r * DH + c * 8;
            CP16(st + so,         g_k_h + g);
            CP16(st + 8192 + so,  g_k_l + g);
            CP16(st + 16384 + so, g_v_h + g);
            CP16(st + 24576 + so, g_v_l + g);
        }
        CPCOMMIT();
    }
    // stage Q (one-time)
    for (int i = tid; i < 1024; i += 128) {
        const int r = i >> 3, c = i & 7;
        const uint32_t so = SWZ((uint32_t)r * 128 + (uint32_t)c * 16);
        const size_t g = hbase + (size_t)(q0 + r) * DH + c * 8;
        uint4 v;
        v = *(const uint4*)(g_q_h + g); STS128(sQh + so, v);
        v = *(const uint4*)(g_q_l + g); STS128(sQl + so, v);
    }
    __syncthreads();

    // Q fragments (persistent): 2 m-frags x 4 k-steps, hi & lo
    uint32_t qh[2][4][4], ql[2][4][4];
#pragma unroll
    for (int mi = 0; mi < 2; mi++) {
        const uint32_t qoff =
            (uint32_t)(wid * 32 + mi * 16 + (lane & 15)) * 128 + ((lane >> 4) << 4);
#pragma unroll
        for (int ks = 0; ks < 4; ks++) {
            LDSM_X4(qh[mi][ks], sQh + SWZ(qoff + ks * 32));
            LDSM_X4(ql[mi][ks], sQl + SWZ(qoff + ks * 32));
        }
    }

    float O[2][8][4];
#pragma unroll
    for (int mi = 0; mi < 2; mi++)
#pragma unroll
        for (int nt = 0; nt < 8; nt++)
#pragma unroll
            for (int e = 0; e < 4; e++) O[mi][nt][e] = 0.f;
    float m_i[2][2], l_i[2][2];
#pragma unroll
    for (int mi = 0; mi < 2; mi++) {
        m_i[mi][0] = m_i[mi][1] = -3.0e38f;
        l_i[mi][0] = l_i[mi][1] = 0.f;
    }

    const int krow = (lane & 7) + ((lane >> 4) << 3);
    const uint32_t kchunk = (((uint32_t)lane >> 3) & 1) << 4;
    const int vrow_l = lane & 15;
    const uint32_t vchunk = ((uint32_t)lane >> 4) << 4;

    for (int kt = 0; kt < SEQ / 64; kt++) {
        CPWAIT0();
        __syncthreads();

        if (kt + 1 < SEQ / 64) {
            const size_t rb = hbase + (size_t)((kt + 1) << 6) * DH;
            const uint32_t st = sStage + ((kt + 1) & 1) * 32768;
#pragma unroll
            for (int j = 0; j < 4; j++) {
                const int idx = tid + (j << 7);
                const int r = idx >> 3, c = idx & 7;
                const uint32_t so = SWZ((uint32_t)r * 128 + (uint32_t)c * 16);
                const size_t g = rb + (size_t)r * DH + c * 8;
                CP16(st + so,         g_k_h + g);
                CP16(st + 8192 + so,  g_k_l + g);
                CP16(st + 16384 + so, g_v_h + g);
                CP16(st + 24576 + so, g_v_l + g);
            }
            CPCOMMIT();
        }

        const uint32_t stK_h = sStage + (kt & 1) * 32768;
        const uint32_t stK_l = stK_h + 8192;
        const uint32_t stV_h = stK_h + 16384;
        const uint32_t stV_l = stK_h + 24576;

        // ---- S = Qhi*Khi + Qhi*Klo + Qlo*Khi ----
        float S[2][8][4];
#pragma unroll
        for (int mi = 0; mi < 2; mi++)
#pragma unroll
            for (int nt = 0; nt < 8; nt++)
#pragma unroll
                for (int e = 0; e < 4; e++) S[mi][nt][e] = 0.f;

#pragma unroll
        for (int ks = 0; ks < 4; ks++) {
            uint32_t kbh[4][4], kbl[4][4];
#pragma unroll
            for (int g = 0; g < 4; g++) {
                const uint32_t off = SWZ((uint32_t)(g * 16 + krow) * 128 + (ks << 5) + kchunk);
                LDSM_X4(kbh[g], stK_h + off);
                LDSM_X4(kbl[g], stK_l + off);
            }
#pragma unroll
            for (int pass = 0; pass < 3; pass++)
#pragma unroll
                for (int g = 0; g < 4; g++)
#pragma unroll
                    for (int mi = 0; mi < 2; mi++) {
                        const uint32_t* a = (pass == 2) ? ql[mi][ks] : qh[mi][ks];
                        const uint32_t* b = (pass == 1) ? kbl[g] : kbh[g];
                        MMA16816(S[mi][2 * g],     a, &b[0]);
                        MMA16816(S[mi][2 * g + 1], a, &b[2]);
                    }
        }

        // ---- online softmax per m-frag ----
#pragma unroll
        for (int mi = 0; mi < 2; mi++) {
            float rx0 = -3.0e38f, rx1 = -3.0e38f;
#pragma unroll
            for (int nt = 0; nt < 8; nt++) {
                rx0 = fmaxf(rx0, fmaxf(S[mi][nt][0], S[mi][nt][1]));
                rx1 = fmaxf(rx1, fmaxf(S[mi][nt][2], S[mi][nt][3]));
            }
            rx0 = fmaxf(rx0, __shfl_xor_sync(0xffffffffu, rx0, 1));
            rx0 = fmaxf(rx0, __shfl_xor_sync(0xffffffffu, rx0, 2));
            rx1 = fmaxf(rx1, __shfl_xor_sync(0xffffffffu, rx1, 1));
            rx1 = fmaxf(rx1, __shfl_xor_sync(0xffffffffu, rx1, 2));
            const float mn0 = fmaxf(m_i[mi][0], rx0), mn1 = fmaxf(m_i[mi][1], rx1);
            const float a0 = __expf(m_i[mi][0] - mn0), a1 = __expf(m_i[mi][1] - mn1);
            float s0 = 0.f, s1 = 0.f;
#pragma unroll
            for (int nt = 0; nt < 8; nt++) {
                S[mi][nt][0] = __expf(S[mi][nt][0] - mn0);
                S[mi][nt][1] = __expf(S[mi][nt][1] - mn0);
                S[mi][nt][2] = __expf(S[mi][nt][2] - mn1);
                S[mi][nt][3] = __expf(S[mi][nt][3] - mn1);
                s0 += S[mi][nt][0] + S[mi][nt][1];
                s1 += S[mi][nt][2] + S[mi][nt][3];
            }
            s0 += __shfl_xor_sync(0xffffffffu, s0, 1);
            s0 += __shfl_xor_sync(0xffffffffu, s0, 2);
            s1 += __shfl_xor_sync(0xffffffffu, s1, 1);
            s1 += __shfl_xor_sync(0xffffffffu, s1, 2);
            l_i[mi][0] = l_i[mi][0] * a0 + s0;
            l_i[mi][1] = l_i[mi][1] * a1 + s1;
            m_i[mi][0] = mn0; m_i[mi][1] = mn1;
#pragma unroll
            for (int nt = 0; nt < 8; nt++) {
                O[mi][nt][0] *= a0; O[mi][nt][1] *= a0;
                O[mi][nt][2] *= a1; O[mi][nt][3] *= a1;
            }
        }

        // ---- PV: O += Ph*Vh + Pl*Vh + Ph*Vl (V^T via ldmatrix.trans) ----
#pragma unroll
        for (int c = 0; c < 4; c++) {
            uint32_t ph[2][4], pl[2][4];
#pragma unroll
            for (int mi = 0; mi < 2; mi++)
#pragma unroll
                for (int j = 0; j < 4; j++) {
                    const int nt = 2 * c + (j >> 1);
                    const int e0 = (j & 1) * 2;
                    const float p0 = S[mi][nt][e0], p1 = S[mi][nt][e0 + 1];
                    const __nv_bfloat16 b0 = __float2bfloat16(p0);
                    const __nv_bfloat16 b1 = __float2bfloat16(p1);
                    ph[mi][j] = bf2u(b0, b1);
                    pl[mi][j] = bf2u(__float2bfloat16(p0 - __bfloat162float(b0)),
                                     __float2bfloat16(p1 - __bfloat162float(b1)));
                }
            uint32_t vbh[4][4], vbl[4][4];
#pragma unroll
            for (int g = 0; g < 4; g++) {
                const uint32_t off =
                    SWZ((uint32_t)(c * 16 + vrow_l) * 128 + ((uint32_t)g << 5) + vchunk);
                LDSM_X4T(vbh[g], stV_h + off);
                LDSM_X4T(vbl[g], stV_l + off);
            }
#pragma unroll
            for (int pass = 0; pass < 3; pass++)
#pragma unroll
                for (int g = 0; g < 4; g++)
#pragma unroll
                    for (int mi = 0; mi < 2; mi++) {
                        const uint32_t* a = (pass == 1) ? pl[mi] : ph[mi];
                        const uint32_t* b = (pass == 2) ? vbl[g] : vbh[g];
                        MMA16816(O[mi][2 * g],     a, &b[0]);
                        MMA16816(O[mi][2 * g + 1], a, &b[2]);
                    }
        }
    }

    // ---- finalize: O/l -> fp16 hi/lo -> g_attn [b][s][h*64+d] ----
    const int b_ = bh >> 4, h_ = bh & 15;
#pragma unroll
    for (int mi = 0; mi < 2; mi++) {
        const float inv0 = 1.0f / l_i[mi][0], inv1 = 1.0f / l_i[mi][1];
        const int row0 = q0 + wid * 32 + mi * 16 + (lane >> 2);
#pragma unroll
        for (int nt = 0; nt < 8; nt++) {
            const int dcol = nt * 8 + ((lane & 3) << 1);
#pragma unroll
            for (int hh = 0; hh < 2; hh++) {
                const int row = row0 + hh * 8;
                const float inv = hh ? inv1 : inv0;
                const float v0 = O[mi][nt][hh * 2 + 0] * inv;
                const float v1 = O[mi][nt][hh * 2 + 1] * inv;
                const __half h0 = __float2half(v0);
                const __half h1 = __float2half(v1);
                const size_t off = ((size_t)b_ * SEQ + row) * HID + h_ * DH + dcol;
                *(uint32_t*)(g_attn_h + off) = h2u(h0, h1);
                *(uint32_t*)(g_attn_l + off) =
                    h2u(__float2half(v0 - __half2float(h0)),
                        __float2half(v1 - __half2float(h1)));
            }
        }
    }
}

// ---------------------------------------------------------------------------
extern "C" void kernel_launch(void* const* d_in, const int* in_sizes, int n_in,
                              void* d_out, int out_size)
{
    const float* x    = (const float*)d_in[0];
    const float* Wqkv = (const float*)d_in[1];
    const float* bqkv = (const float*)d_in[2];
    const float* Wout = (const float*)d_in[3];
    const float* bout = (const float*)d_in[4];
    float* out = (float*)d_out;

    cudaFuncSetAttribute(gemm_tc,
                         cudaFuncAttributeMaxDynamicSharedMemorySize, GT_SMEM);
    cudaFuncSetAttribute(attn_mma,
                         cudaFuncAttributeMaxDynamicSharedMemorySize, AT_SMEM);

    __half *xh, *xl, *wqh, *woh, *ath, *atl;
    cudaGetSymbolAddress((void**)&xh,  g_x_h);
    cudaGetSymbolAddress((void**)&xl,  g_x_l);
    cudaGetSymbolAddress((void**)&wqh, g_wq_h);
    cudaGetSymbolAddress((void**)&woh, g_wo_h);
    cudaGetSymbolAddress((void**)&ath, g_attn_h);
    cudaGetSymbolAddress((void**)&atl, g_attn_l);

    // 0) prep: split x (fp16 hi/lo); transpose weights to fp16
    split_f16<<<(MTOT * HID / 4 + 255) / 256, 256>>>(x, xh, xl, MTOT * HID / 4);
    transpose_h<<<dim3(3 * HID / 32, HID / 32), dim3(32, 8)>>>(Wqkv, wqh, HID, 3 * HID);
    transpose_h<<<dim3(HID / 32, HID / 32), dim3(32, 8)>>>(Wout, woh, HID, HID);

    // 1) QKV projection (fp16 2-pass) -> Q/K/V bf16 hi/lo (Q pre-scaled by 1/8)
    gemm_tc<<<dim3(3 * HID / 128, MTOT / 128), 256, GT_SMEM>>>(
        xh, xl, wqh, bqkv, nullptr, MTOT, 3 * HID, HID, 1);

    // 2) Tensor-core flash attention (bf16 3-pass) -> g_attn fp16 hi/lo
    attn_mma<<<dim3(SEQ / 128, NBH), 128, AT_SMEM>>>();

    // 3) Output projection (fp16 2-pass) + bias -> out
    gemm_tc<<<dim3(HID / 128, MTOT / 128), 256, GT_SMEM>>>(
        ath, atl, woh, bout, out, MTOT, HID, HID, 0);
}

// round 16
// speedup vs baseline: 1.4022x; 1.1942x over previous
#include <cuda_runtime.h>
#include <cuda_bf16.h>
#include <cuda_fp16.h>
#include <cstdint>
#include <math.h>

// Problem constants
#define BATCH   2
#define SEQ     2048
#define HID     1024
#define HEADS   16
#define DH      64
#define MTOT    (BATCH * SEQ)          // 4096
#define NBH     (BATCH * HEADS)        // 32

// ---------------------------------------------------------------------------
// Scratch (device globals — no allocation allowed)
// ---------------------------------------------------------------------------
#define QKV_ELEMS ((size_t)NBH * SEQ * DH)
__device__ __half g_q_h[QKV_ELEMS], g_q_l[QKV_ELEMS];
__device__ __half g_k_h[QKV_ELEMS];
__device__ __half g_v_h[QKV_ELEMS], g_v_l[QKV_ELEMS];
__device__ __half g_attn_h[(size_t)MTOT * HID];
__device__ __half g_attn_l[(size_t)MTOT * HID];
__device__ __half g_x_h[(size_t)MTOT * HID];
__device__ __half g_x_l[(size_t)MTOT * HID];
__device__ __half g_wq_h[(size_t)3 * HID * HID];   // [3072][1024] = fp16(W_qkv^T)
__device__ __half g_wo_h[(size_t)HID * HID];       // [1024][1024] = fp16(W_out^T)

// ---------------------------------------------------------------------------
// PTX helpers (baseline sm_103 ISA: ldmatrix + mma.sync + cp.async)
// ---------------------------------------------------------------------------
__device__ __forceinline__ uint32_t smem_u32(const void* p) {
    uint32_t a;
    asm("{ .reg .u64 t; cvta.to.shared.u64 t, %1; cvt.u32.u64 %0, t; }" : "=r"(a) : "l"(p));
    return a;
}
#define SWZ(o) ((o) ^ (((o) >> 3) & 0x70))
#define STS128(addr, v) \
    asm volatile("st.shared.v4.b32 [%0], {%1,%2,%3,%4};" \
                 :: "r"(addr), "r"(v.x), "r"(v.y), "r"(v.z), "r"(v.w) : "memory")

#define LDSM_X4(r, addr) \
    asm volatile("ldmatrix.sync.aligned.m8n8.x4.shared.b16 {%0,%1,%2,%3}, [%4];" \
        : "=r"((r)[0]), "=r"((r)[1]), "=r"((r)[2]), "=r"((r)[3]) : "r"(addr))
#define LDSM_X4T(r, addr) \
    asm volatile("ldmatrix.sync.aligned.m8n8.x4.trans.shared.b16 {%0,%1,%2,%3}, [%4];" \
        : "=r"((r)[0]), "=r"((r)[1]), "=r"((r)[2]), "=r"((r)[3]) : "r"(addr))
#define LDSM_X2(r, addr) \
    asm volatile("ldmatrix.sync.aligned.m8n8.x2.shared.b16 {%0,%1}, [%2];" \
        : "=r"((r)[0]), "=r"((r)[1]) : "r"(addr))
// fp16 mma (all stages)
#define MMAF16(d, a, b) \
    asm volatile("mma.sync.aligned.m16n8k16.row.col.f32.f16.f16.f32 " \
        "{%0,%1,%2,%3}, {%4,%5,%6,%7}, {%8,%9}, {%0,%1,%2,%3};" \
        : "+f"((d)[0]), "+f"((d)[1]), "+f"((d)[2]), "+f"((d)[3]) \
        : "r"((a)[0]), "r"((a)[1]), "r"((a)[2]), "r"((a)[3]), \
          "r"((b)[0]), "r"((b)[1]))

#define CP16(dst, src) \
    asm volatile("cp.async.cg.shared.global [%0], [%1], 16;" :: "r"(dst), "l"(src) : "memory")
#define CPCOMMIT() asm volatile("cp.async.commit_group;" ::: "memory")
#define CPWAIT0()  asm volatile("cp.async.wait_group 0;" ::: "memory")

__device__ __forceinline__ uint32_t h2u(__half lo, __half hi) {
    union { __half2 h; uint32_t u; } c;
    c.h = __halves2half2(lo, hi);
    return c.u;
}

// ---------------------------------------------------------------------------
// Prep kernels: fp32 -> fp16 hi/lo split; W[K][N] -> fp16(W^T)[N][K]
// ---------------------------------------------------------------------------
__global__ __launch_bounds__(256) void split_f16(
    const float* __restrict__ s, __half* __restrict__ hi,
    __half* __restrict__ lo, int n4)
{
    int i = blockIdx.x * 256 + threadIdx.x;
    if (i >= n4) return;
    float4 v = ((const float4*)s)[i];
    union { __half b[4]; uint2 u; } ph, pl;
    float f[4] = {v.x, v.y, v.z, v.w};
#pragma unroll
    for (int j = 0; j < 4; j++) {
        __half h = __float2half(f[j]);
        ph.b[j] = h;
        pl.b[j] = __float2half(f[j] - __half2float(h));
    }
    ((uint2*)hi)[i] = ph.u;
    ((uint2*)lo)[i] = pl.u;
}

__global__ void transpose_h(const float* __restrict__ W,
                            __half* __restrict__ Th, int K, int N)
{
    __shared__ float t[32][33];
    const int k0 = blockIdx.y * 32, n0 = blockIdx.x * 32;
    const int tx = threadIdx.x, ty = threadIdx.y;
    for (int j = ty; j < 32; j += 8)
        t[j][tx] = W[(size_t)(k0 + j) * N + n0 + tx];
    __syncthreads();
    for (int j = ty; j < 32; j += 8)
        Th[(size_t)(n0 + j) * K + k0 + tx] = __float2half(t[tx][j]);
}

// ---------------------------------------------------------------------------
// mma.sync GEMM, fp16 2-pass (A 22-bit via hi/lo, W 11-bit), fp32 accumulate.
// cp.async 2-stage pipelined mainloop (K-chunk 64, 48KB/stage).
// C[M,N] = A[M,K] @ B[N,K]^T + bias[N]
// mode 0: plain f32 write to C.  mode 1: write Q/K/V fp16 (Q,V hi/lo; K hi).
// ---------------------------------------------------------------------------
#define GT_SMEM (2 * 49152 + 1024)

__global__ __launch_bounds__(256, 1) void gemm_tc(
    const __half* __restrict__ Ah, const __half* __restrict__ Al,
    const __half* __restrict__ Bh,
    const float* __restrict__ bias, float* __restrict__ C,
    int M, int N, int K, int mode)
{
    extern __shared__ char smraw[];
    const uint32_t tile = (smem_u32(smraw) + 1023u) & ~1023u;
    // stage s at tile + s*49152: A_h 0 | A_l 16K | B_h 32K

    const int tid  = threadIdx.x;
    const int wid  = tid >> 5, lane = tid & 31;
    const int wm   = wid & 1, wn = wid >> 1;        // 2 x 4 warp grid
    const int bm   = blockIdx.y << 7, bn = blockIdx.x << 7;

    uint32_t a_base[4], b_base[4];
#pragma unroll
    for (int mi = 0; mi < 4; mi++) {
        const int rowA = wm * 64 + mi * 16 + (lane & 15);
        a_base[mi] = (uint32_t)rowA * 128 + (((uint32_t)lane >> 4) << 4);
    }
    const int l15 = lane & 15;
#pragma unroll
    for (int ni = 0; ni < 4; ni++) {
        const int rowB = wn * 32 + ni * 8 + (l15 & 7);
        b_base[ni] = (uint32_t)rowB * 128 + (((uint32_t)l15 >> 3) << 4);
    }

    float d[4][4][4];
#pragma unroll
    for (int mi = 0; mi < 4; mi++)
#pragma unroll
        for (int ni = 0; ni < 4; ni++)
#pragma unroll
            for (int k = 0; k < 4; k++) d[mi][ni][k] = 0.f;

    // ---- prologue: issue chunk 0 into stage 0 ----
    {
        const uint32_t st = tile;
#pragma unroll
        for (int i = 0; i < 4; i++) {
            const int idx = tid + (i << 8);
            const int r = idx >> 3, c = idx & 7;
            const uint32_t so = SWZ((uint32_t)r * 128 + (uint32_t)c * 16);
            const size_t gA = (size_t)(bm + r) * K + c * 8;
            const size_t gB = (size_t)(bn + r) * K + c * 8;
            CP16(st + so,         Ah + gA);
            CP16(st + 16384 + so, Al + gA);
            CP16(st + 32768 + so, Bh + gB);
        }
        CPCOMMIT();
    }

    int stg = 0;
    for (int kc = 0; kc < K; kc += 64, stg ^= 1) {
        CPWAIT0();
        __syncthreads();

        if (kc + 64 < K) {
            const uint32_t st = tile + (uint32_t)(stg ^ 1) * 49152u;
#pragma unroll
            for (int i = 0; i < 4; i++) {
                const int idx = tid + (i << 8);
                const int r = idx >> 3, c = idx & 7;
                const uint32_t so = SWZ((uint32_t)r * 128 + (uint32_t)c * 16);
                const size_t gA = (size_t)(bm + r) * K + kc + 64 + c * 8;
                const size_t gB = (size_t)(bn + r) * K + kc + 64 + c * 8;
                CP16(st + so,         Ah + gA);
                CP16(st + 16384 + so, Al + gA);
                CP16(st + 32768 + so, Bh + gB);
            }
            CPCOMMIT();
        }

        const uint32_t sA_h = tile + (uint32_t)stg * 49152u;
        const uint32_t sA_l = sA_h + 16384, sB_h = sA_h + 32768;

#pragma unroll
        for (int ks = 0; ks < 4; ks++) {
            const uint32_t kb = (uint32_t)ks << 5;
            uint32_t fAh[4][4], fAl[4][4], fBh[4][2];
#pragma unroll
            for (int mi = 0; mi < 4; mi++) {
                LDSM_X4(fAh[mi], sA_h + SWZ(a_base[mi] + kb));
                LDSM_X4(fAl[mi], sA_l + SWZ(a_base[mi] + kb));
            }
#pragma unroll
            for (int ni = 0; ni < 4; ni++)
                LDSM_X2(fBh[ni], sB_h + SWZ(b_base[ni] + kb));
#pragma unroll
            for (int pass = 0; pass < 2; pass++)
#pragma unroll
                for (int mi = 0; mi < 4; mi++)
#pragma unroll
                    for (int ni = 0; ni < 4; ni++) {
                        const uint32_t* a = (pass == 0) ? fAh[mi] : fAl[mi];
                        MMAF16(d[mi][ni], a, fBh[ni]);
                    }
        }
    }

    // ---- epilogue ----
    const int q = lane >> 2;
    const int cpair = (lane & 3) << 1;
#pragma unroll
    for (int ni = 0; ni < 4; ni++) {
        const int n = bn + wn * 32 + ni * 8 + cpair;
        const float2 bs = *(const float2*)(bias + n);
#pragma unroll
        for (int mi = 0; mi < 4; mi++) {
#pragma unroll
            for (int hh = 0; hh < 2; hh++) {
                const int m = bm + wm * 64 + mi * 16 + q + hh * 8;
                float2 v;
                v.x = d[mi][ni][hh * 2 + 0] + bs.x;
                v.y = d[mi][ni][hh * 2 + 1] + bs.y;
                if (mode == 1) {
                    const int cc = n >> 10, hd = (n >> 6) & 15, dd = n & 63;
                    const int bb = m >> 11, ss = m & 2047;
                    const float sc = (cc == 0) ? 0.125f : 1.0f;
                    const float vx = v.x * sc, vy = v.y * sc;
                    const __half hx = __float2half(vx);
                    const __half hy = __float2half(vy);
                    const size_t off = ((size_t)(bb * HEADS + hd) * SEQ + ss) * DH + dd;
                    __half* dh = (cc == 0) ? g_q_h : (cc == 1) ? g_k_h : g_v_h;
                    *(uint32_t*)(dh + off) = h2u(hx, hy);
                    if (cc != 1) {
                        __half* dl = (cc == 0) ? g_q_l : g_v_l;
                        *(uint32_t*)(dl + off) =
                            h2u(__float2half(vx - __half2float(hx)),
                                __float2half(vy - __half2float(hy)));
                    }
                } else {
                    *(float2*)(C + (size_t)m * N + n) = v;
                }
            }
        }
    }
}

// ---------------------------------------------------------------------------
// Tensor-core flash attention, fp16 2-pass everywhere:
//   QK^T = Qh*K + Ql*K       (Q 22-bit, K 11-bit)
//   PV   = P*Vh + P*Vl       (P 11-bit, V 22-bit)
// 128 threads / 4 warps, 128 q-rows per CTA, 2 CTAs/SM. 64-key tiles,
// cp.async double-buffered (3 buffers/stage: Kh, Vh, Vl -> 24KB/stage).
// smem: Qh 16K | Ql 16K | 2 x 24K stages = 80K.
// ---------------------------------------------------------------------------
#define AT_SMEM (80 * 1024 + 1024)

__global__ __launch_bounds__(128, 2) void attn_mma()
{
    extern __shared__ char smraw[];
    const uint32_t base = (smem_u32(smraw) + 1023u) & ~1023u;
    const uint32_t sQh = base, sQl = base + 16384;
    const uint32_t sStage = base + 32768;  // + s*24576: Kh 0 | Vh 8K | Vl 16K

    const int tid = threadIdx.x, lane = tid & 31, wid = tid >> 5;
    const int bh = blockIdx.y;
    const int q0 = blockIdx.x << 7;
    const size_t hbase = (size_t)bh * (SEQ * DH);

    // ---- prologue: cp.async key-tile 0 ----
    {
        const uint32_t st = sStage;
#pragma unroll
        for (int j = 0; j < 4; j++) {
            const int idx = tid + (j << 7);        // 0..511
            const int r = idx >> 3, c = idx & 7;
            const uint32_t so = SWZ((uint32_t)r * 128 + (uint32_t)c * 16);
            const size_t g = hbase + (size_t)r * DH + c * 8;
            CP16(st + so,         g_k_h + g);
            CP16(st + 8192 + so,  g_v_h + g);
            CP16(st + 16384 + so, g_v_l + g);
        }
        CPCOMMIT();
    }
    // stage Q (one-time)
    for (int i = tid; i < 1024; i += 128) {
        const int r = i >> 3, c = i & 7;
        const uint32_t so = SWZ((uint32_t)r * 128 + (uint32_t)c * 16);
        const size_t g = hbase + (size_t)(q0 + r) * DH + c * 8;
        uint4 v;
        v = *(const uint4*)(g_q_h + g); STS128(sQh + so, v);
        v = *(const uint4*)(g_q_l + g); STS128(sQl + so, v);
    }
    __syncthreads();

    // Q fragments (persistent): 2 m-frags x 4 k-steps, hi & lo
    uint32_t qh[2][4][4], ql[2][4][4];
#pragma unroll
    for (int mi = 0; mi < 2; mi++) {
        const uint32_t qoff =
            (uint32_t)(wid * 32 + mi * 16 + (lane & 15)) * 128 + ((lane >> 4) << 4);
#pragma unroll
        for (int ks = 0; ks < 4; ks++) {
            LDSM_X4(qh[mi][ks], sQh + SWZ(qoff + ks * 32));
            LDSM_X4(ql[mi][ks], sQl + SWZ(qoff + ks * 32));
        }
    }

    float O[2][8][4];
#pragma unroll
    for (int mi = 0; mi < 2; mi++)
#pragma unroll
        for (int nt = 0; nt < 8; nt++)
#pragma unroll
            for (int e = 0; e < 4; e++) O[mi][nt][e] = 0.f;
    float m_i[2][2], l_i[2][2];
#pragma unroll
    for (int mi = 0; mi < 2; mi++) {
        m_i[mi][0] = m_i[mi][1] = -3.0e38f;
        l_i[mi][0] = l_i[mi][1] = 0.f;
    }

    const int krow = (lane & 7) + ((lane >> 4) << 3);
    const uint32_t kchunk = (((uint32_t)lane >> 3) & 1) << 4;
    const int vrow_l = lane & 15;
    const uint32_t vchunk = ((uint32_t)lane >> 4) << 4;

    for (int kt = 0; kt < SEQ / 64; kt++) {
        CPWAIT0();
        __syncthreads();

        if (kt + 1 < SEQ / 64) {
            const size_t rb = hbase + (size_t)((kt + 1) << 6) * DH;
            const uint32_t st = sStage + ((kt + 1) & 1) * 24576;
#pragma unroll
            for (int j = 0; j < 4; j++) {
                const int idx = tid + (j << 7);
                const int r = idx >> 3, c = idx & 7;
                const uint32_t so = SWZ((uint32_t)r * 128 + (uint32_t)c * 16);
                const size_t g = rb + (size_t)r * DH + c * 8;
                CP16(st + so,         g_k_h + g);
                CP16(st + 8192 + so,  g_v_h + g);
                CP16(st + 16384 + so, g_v_l + g);
            }
            CPCOMMIT();
        }

        const uint32_t stK_h = sStage + (kt & 1) * 24576;
        const uint32_t stV_h = stK_h + 8192;
        const uint32_t stV_l = stK_h + 16384;

        // ---- S = Qh*K + Ql*K  (2 passes) ----
        float S[2][8][4];
#pragma unroll
        for (int mi = 0; mi < 2; mi++)
#pragma unroll
            for (int nt = 0; nt < 8; nt++)
#pragma unroll
                for (int e = 0; e < 4; e++) S[mi][nt][e] = 0.f;

#pragma unroll
        for (int ks = 0; ks < 4; ks++) {
            uint32_t kbh[4][4];
#pragma unroll
            for (int g = 0; g < 4; g++) {
                const uint32_t off = SWZ((uint32_t)(g * 16 + krow) * 128 + (ks << 5) + kchunk);
                LDSM_X4(kbh[g], stK_h + off);
            }
#pragma unroll
            for (int pass = 0; pass < 2; pass++)
#pragma unroll
                for (int g = 0; g < 4; g++)
#pragma unroll
                    for (int mi = 0; mi < 2; mi++) {
                        const uint32_t* a = (pass == 0) ? qh[mi][ks] : ql[mi][ks];
                        MMAF16(S[mi][2 * g],     a, &kbh[g][0]);
                        MMAF16(S[mi][2 * g + 1], a, &kbh[g][2]);
                    }
        }

        // ---- online softmax per m-frag ----
#pragma unroll
        for (int mi = 0; mi < 2; mi++) {
            float rx0 = -3.0e38f, rx1 = -3.0e38f;
#pragma unroll
            for (int nt = 0; nt < 8; nt++) {
                rx0 = fmaxf(rx0, fmaxf(S[mi][nt][0], S[mi][nt][1]));
                rx1 = fmaxf(rx1, fmaxf(S[mi][nt][2], S[mi][nt][3]));
            }
            rx0 = fmaxf(rx0, __shfl_xor_sync(0xffffffffu, rx0, 1));
            rx0 = fmaxf(rx0, __shfl_xor_sync(0xffffffffu, rx0, 2));
            rx1 = fmaxf(rx1, __shfl_xor_sync(0xffffffffu, rx1, 1));
            rx1 = fmaxf(rx1, __shfl_xor_sync(0xffffffffu, rx1, 2));
            const float mn0 = fmaxf(m_i[mi][0], rx0), mn1 = fmaxf(m_i[mi][1], rx1);
            const float a0 = __expf(m_i[mi][0] - mn0), a1 = __expf(m_i[mi][1] - mn1);
            float s0 = 0.f, s1 = 0.f;
#pragma unroll
            for (int nt = 0; nt < 8; nt++) {
                S[mi][nt][0] = __expf(S[mi][nt][0] - mn0);
                S[mi][nt][1] = __expf(S[mi][nt][1] - mn0);
                S[mi][nt][2] = __expf(S[mi][nt][2] - mn1);
                S[mi][nt][3] = __expf(S[mi][nt][3] - mn1);
                s0 += S[mi][nt][0] + S[mi][nt][1];
                s1 += S[mi][nt][2] + S[mi][nt][3];
            }
            s0 += __shfl_xor_sync(0xffffffffu, s0, 1);
            s0 += __shfl_xor_sync(0xffffffffu, s0, 2);
            s1 += __shfl_xor_sync(0xffffffffu, s1, 1);
            s1 += __shfl_xor_sync(0xffffffffu, s1, 2);
            l_i[mi][0] = l_i[mi][0] * a0 + s0;
            l_i[mi][1] = l_i[mi][1] * a1 + s1;
            m_i[mi][0] = mn0; m_i[mi][1] = mn1;
#pragma unroll
            for (int nt = 0; nt < 8; nt++) {
                O[mi][nt][0] *= a0; O[mi][nt][1] *= a0;
                O[mi][nt][2] *= a1; O[mi][nt][3] *= a1;
            }
        }

        // ---- PV: O += P*Vh + P*Vl  (2 passes; V^T via ldmatrix.trans) ----
#pragma unroll
        for (int c = 0; c < 4; c++) {
            uint32_t ph[2][4];
#pragma unroll
            for (int mi = 0; mi < 2; mi++)
#pragma unroll
                for (int j = 0; j < 4; j++) {
                    const int nt = 2 * c + (j >> 1);
                    const int e0 = (j & 1) * 2;
                    ph[mi][j] = h2u(__float2half(S[mi][nt][e0]),
                                    __float2half(S[mi][nt][e0 + 1]));
                }
            uint32_t vbh[4][4], vbl[4][4];
#pragma unroll
            for (int g = 0; g < 4; g++) {
                const uint32_t off =
                    SWZ((uint32_t)(c * 16 + vrow_l) * 128 + ((uint32_t)g << 5) + vchunk);
                LDSM_X4T(vbh[g], stV_h + off);
                LDSM_X4T(vbl[g], stV_l + off);
            }
#pragma unroll
            for (int pass = 0; pass < 2; pass++)
#pragma unroll
                for (int g = 0; g < 4; g++)
#pragma unroll
                    for (int mi = 0; mi < 2; mi++) {
                        const uint32_t* b = (pass == 0) ? vbh[g] : vbl[g];
                        MMAF16(O[mi][2 * g],     ph[mi], &b[0]);
                        MMAF16(O[mi][2 * g + 1], ph[mi], &b[2]);
                    }
        }
    }

    // ---- finalize: O/l -> fp16 hi/lo -> g_attn [b][s][h*64+d] ----
    const int b_ = bh >> 4, h_ = bh & 15;
#pragma unroll
    for (int mi = 0; mi < 2; mi++) {
        const float inv0 = 1.0f / l_i[mi][0], inv1 = 1.0f / l_i[mi][1];
        const int row0 = q0 + wid * 32 + mi * 16 + (lane >> 2);
#pragma unroll
        for (int nt = 0; nt < 8; nt++) {
            const int dcol = nt * 8 + ((lane & 3) << 1);
#pragma unroll
            for (int hh = 0; hh < 2; hh++) {
                const int row = row0 + hh * 8;
                const float inv = hh ? inv1 : inv0;
                const float v0 = O[mi][nt][hh * 2 + 0] * inv;
                const float v1 = O[mi][nt][hh * 2 + 1] * inv;
                const __half h0 = __float2half(v0);
                const __half h1 = __float2half(v1);
                const size_t off = ((size_t)b_ * SEQ + row) * HID + h_ * DH + dcol;
                *(uint32_t*)(g_attn_h + off) = h2u(h0, h1);
                *(uint32_t*)(g_attn_l + off) =
                    h2u(__float2half(v0 - __half2float(h0)),
                        __float2half(v1 - __half2float(h1)));
            }
        }
    }
}

// ---------------------------------------------------------------------------
extern "C" void kernel_launch(void* const* d_in, const int* in_sizes, int n_in,
                              void* d_out, int out_size)
{
    const float* x    = (const float*)d_in[0];
    const float* Wqkv = (const float*)d_in[1];
    const float* bqkv = (const float*)d_in[2];
    const float* Wout = (const float*)d_in[3];
    const float* bout = (const float*)d_in[4];
    float* out = (float*)d_out;

    cudaFuncSetAttribute(gemm_tc,
                         cudaFuncAttributeMaxDynamicSharedMemorySize, GT_SMEM);
    cudaFuncSetAttribute(attn_mma,
                         cudaFuncAttributeMaxDynamicSharedMemorySize, AT_SMEM);

    __half *xh, *xl, *wqh, *woh, *ath, *atl;
    cudaGetSymbolAddress((void**)&xh,  g_x_h);
    cudaGetSymbolAddress((void**)&xl,  g_x_l);
    cudaGetSymbolAddress((void**)&wqh, g_wq_h);
    cudaGetSymbolAddress((void**)&woh, g_wo_h);
    cudaGetSymbolAddress((void**)&ath, g_attn_h);
    cudaGetSymbolAddress((void**)&atl, g_attn_l);

    // 0) prep: split x (fp16 hi/lo); transpose weights to fp16
    split_f16<<<(MTOT * HID / 4 + 255) / 256, 256>>>(x, xh, xl, MTOT * HID / 4);
    transpose_h<<<dim3(3 * HID / 32, HID / 32), dim3(32, 8)>>>(Wqkv, wqh, HID, 3 * HID);
    transpose_h<<<dim3(HID / 32, HID / 32), dim3(32, 8)>>>(Wout, woh, HID, HID);

    // 1) QKV projection (fp16 2-pass) -> Q/K/V fp16 (Q pre-scaled by 1/8)
    gemm_tc<<<dim3(3 * HID / 128, MTOT / 128), 256, GT_SMEM>>>(
        xh, xl, wqh, bqkv, nullptr, MTOT, 3 * HID, HID, 1);

    // 2) Tensor-core flash attention (fp16 2-pass) -> g_attn fp16 hi/lo
    attn_mma<<<dim3(SEQ / 128, NBH), 128, AT_SMEM>>>();

    // 3) Output projection (fp16 2-pass) + bias -> out
    gemm_tc<<<dim3(HID / 128, MTOT / 128), 256, GT_SMEM>>>(
        ath, atl, woh, bout, out, MTOT, HID, HID, 0);
}

// round 17
// speedup vs baseline: 2.1581x; 1.5390x over previous
#include <cuda_runtime.h>
#include <cuda_bf16.h>
#include <cuda_fp16.h>
#include <cstdint>
#include <math.h>

// Problem constants
#define BATCH   2
#define SEQ     2048
#define HID     1024
#define HEADS   16
#define DH      64
#define MTOT    (BATCH * SEQ)          // 4096
#define NBH     (BATCH * HEADS)        // 32

// ---------------------------------------------------------------------------
// Scratch (device globals — no allocation allowed)
// ---------------------------------------------------------------------------
#define QKV_ELEMS ((size_t)NBH * SEQ * DH)
__device__ __half g_q_h[QKV_ELEMS];
__device__ __half g_k_h[QKV_ELEMS];
__device__ __half g_v_h[QKV_ELEMS];
__device__ __half g_attn_h[(size_t)MTOT * HID];
__device__ __half g_attn_l[(size_t)MTOT * HID];
__device__ __half g_x_h[(size_t)MTOT * HID];
__device__ __half g_wq_h[(size_t)3 * HID * HID];   // [3072][1024] = fp16(W_qkv^T)
__device__ __half g_wo_h[(size_t)HID * HID];       // [1024][1024] = fp16(W_out^T)

// ---------------------------------------------------------------------------
// PTX helpers (baseline sm_103 ISA: ldmatrix + mma.sync + cp.async)
// ---------------------------------------------------------------------------
__device__ __forceinline__ uint32_t smem_u32(const void* p) {
    uint32_t a;
    asm("{ .reg .u64 t; cvta.to.shared.u64 t, %1; cvt.u32.u64 %0, t; }" : "=r"(a) : "l"(p));
    return a;
}
#define SWZ(o) ((o) ^ (((o) >> 3) & 0x70))
#define STS128(addr, v) \
    asm volatile("st.shared.v4.b32 [%0], {%1,%2,%3,%4};" \
                 :: "r"(addr), "r"(v.x), "r"(v.y), "r"(v.z), "r"(v.w) : "memory")

#define LDSM_X4(r, addr) \
    asm volatile("ldmatrix.sync.aligned.m8n8.x4.shared.b16 {%0,%1,%2,%3}, [%4];" \
        : "=r"((r)[0]), "=r"((r)[1]), "=r"((r)[2]), "=r"((r)[3]) : "r"(addr))
#define LDSM_X4T(r, addr) \
    asm volatile("ldmatrix.sync.aligned.m8n8.x4.trans.shared.b16 {%0,%1,%2,%3}, [%4];" \
        : "=r"((r)[0]), "=r"((r)[1]), "=r"((r)[2]), "=r"((r)[3]) : "r"(addr))
#define LDSM_X2(r, addr) \
    asm volatile("ldmatrix.sync.aligned.m8n8.x2.shared.b16 {%0,%1}, [%2];" \
        : "=r"((r)[0]), "=r"((r)[1]) : "r"(addr))
// fp16 mma (all stages)
#define MMAF16(d, a, b) \
    asm volatile("mma.sync.aligned.m16n8k16.row.col.f32.f16.f16.f32 " \
        "{%0,%1,%2,%3}, {%4,%5,%6,%7}, {%8,%9}, {%0,%1,%2,%3};" \
        : "+f"((d)[0]), "+f"((d)[1]), "+f"((d)[2]), "+f"((d)[3]) \
        : "r"((a)[0]), "r"((a)[1]), "r"((a)[2]), "r"((a)[3]), \
          "r"((b)[0]), "r"((b)[1]))

#define CP16(dst, src) \
    asm volatile("cp.async.cg.shared.global [%0], [%1], 16;" :: "r"(dst), "l"(src) : "memory")
#define CPCOMMIT() asm volatile("cp.async.commit_group;" ::: "memory")
#define CPWAIT0()  asm volatile("cp.async.wait_group 0;" ::: "memory")

__device__ __forceinline__ uint32_t h2u(__half lo, __half hi) {
    union { __half2 h; uint32_t u; } c;
    c.h = __halves2half2(lo, hi);
    return c.u;
}

// ---------------------------------------------------------------------------
// Prep kernels: fp32 -> fp16 cast; W[K][N] -> fp16(W^T)[N][K]
// ---------------------------------------------------------------------------
__global__ __launch_bounds__(256) void cast_f16(
    const float* __restrict__ s, __half* __restrict__ hi, int n4)
{
    int i = blockIdx.x * 256 + threadIdx.x;
    if (i >= n4) return;
    float4 v = ((const float4*)s)[i];
    union { __half b[4]; uint2 u; } ph;
    ph.b[0] = __float2half(v.x); ph.b[1] = __float2half(v.y);
    ph.b[2] = __float2half(v.z); ph.b[3] = __float2half(v.w);
    ((uint2*)hi)[i] = ph.u;
}

__global__ void transpose_h(const float* __restrict__ W,
                            __half* __restrict__ Th, int K, int N)
{
    __shared__ float t[32][33];
    const int k0 = blockIdx.y * 32, n0 = blockIdx.x * 32;
    const int tx = threadIdx.x, ty = threadIdx.y;
    for (int j = ty; j < 32; j += 8)
        t[j][tx] = W[(size_t)(k0 + j) * N + n0 + tx];
    __syncthreads();
    for (int j = ty; j < 32; j += 8)
        Th[(size_t)(n0 + j) * K + k0 + tx] = __float2half(t[tx][j]);
}

// ---------------------------------------------------------------------------
// mma.sync fp16 GEMM, fp32 accumulate. 1-pass (Al==nullptr) or 2-pass
// (A 22-bit via hi/lo). cp.async 2-stage pipelined mainloop (K-chunk 64).
// C[M,N] = A[M,K] @ B[N,K]^T + bias[N]
// mode 0: plain f32 write to C.  mode 1: write Q/K/V fp16 (Q pre-scaled).
// ---------------------------------------------------------------------------
#define GT_SMEM (2 * 49152 + 1024)

__global__ __launch_bounds__(256, 1) void gemm_tc(
    const __half* __restrict__ Ah, const __half* __restrict__ Al,
    const __half* __restrict__ Bh,
    const float* __restrict__ bias, float* __restrict__ C,
    int M, int N, int K, int mode)
{
    extern __shared__ char smraw[];
    const uint32_t tile = (smem_u32(smraw) + 1023u) & ~1023u;
    // stage s at tile + s*49152: A_h 0 | A_l 16K | B_h 32K

    const int tid  = threadIdx.x;
    const int wid  = tid >> 5, lane = tid & 31;
    const int wm   = wid & 1, wn = wid >> 1;        // 2 x 4 warp grid
    const int bm   = blockIdx.y << 7, bn = blockIdx.x << 7;
    const bool two = (Al != nullptr);

    uint32_t a_base[4], b_base[4];
#pragma unroll
    for (int mi = 0; mi < 4; mi++) {
        const int rowA = wm * 64 + mi * 16 + (lane & 15);
        a_base[mi] = (uint32_t)rowA * 128 + (((uint32_t)lane >> 4) << 4);
    }
    const int l15 = lane & 15;
#pragma unroll
    for (int ni = 0; ni < 4; ni++) {
        const int rowB = wn * 32 + ni * 8 + (l15 & 7);
        b_base[ni] = (uint32_t)rowB * 128 + (((uint32_t)l15 >> 3) << 4);
    }

    float d[4][4][4];
#pragma unroll
    for (int mi = 0; mi < 4; mi++)
#pragma unroll
        for (int ni = 0; ni < 4; ni++)
#pragma unroll
            for (int k = 0; k < 4; k++) d[mi][ni][k] = 0.f;

    // ---- prologue: issue chunk 0 into stage 0 ----
    {
        const uint32_t st = tile;
#pragma unroll
        for (int i = 0; i < 4; i++) {
            const int idx = tid + (i << 8);
            const int r = idx >> 3, c = idx & 7;
            const uint32_t so = SWZ((uint32_t)r * 128 + (uint32_t)c * 16);
            const size_t gA = (size_t)(bm + r) * K + c * 8;
            const size_t gB = (size_t)(bn + r) * K + c * 8;
            CP16(st + so,         Ah + gA);
            if (two) CP16(st + 16384 + so, Al + gA);
            CP16(st + 32768 + so, Bh + gB);
        }
        CPCOMMIT();
    }

    int stg = 0;
    for (int kc = 0; kc < K; kc += 64, stg ^= 1) {
        CPWAIT0();
        __syncthreads();

        if (kc + 64 < K) {
            const uint32_t st = tile + (uint32_t)(stg ^ 1) * 49152u;
#pragma unroll
            for (int i = 0; i < 4; i++) {
                const int idx = tid + (i << 8);
                const int r = idx >> 3, c = idx & 7;
                const uint32_t so = SWZ((uint32_t)r * 128 + (uint32_t)c * 16);
                const size_t gA = (size_t)(bm + r) * K + kc + 64 + c * 8;
                const size_t gB = (size_t)(bn + r) * K + kc + 64 + c * 8;
                CP16(st + so,         Ah + gA);
                if (two) CP16(st + 16384 + so, Al + gA);
                CP16(st + 32768 + so, Bh + gB);
            }
            CPCOMMIT();
        }

        const uint32_t sA_h = tile + (uint32_t)stg * 49152u;
        const uint32_t sA_l = sA_h + 16384, sB_h = sA_h + 32768;

#pragma unroll
        for (int ks = 0; ks < 4; ks++) {
            const uint32_t kb = (uint32_t)ks << 5;
            uint32_t fAh[4][4], fBh[4][2];
#pragma unroll
            for (int mi = 0; mi < 4; mi++)
                LDSM_X4(fAh[mi], sA_h + SWZ(a_base[mi] + kb));
#pragma unroll
            for (int ni = 0; ni < 4; ni++)
                LDSM_X2(fBh[ni], sB_h + SWZ(b_base[ni] + kb));
#pragma unroll
            for (int mi = 0; mi < 4; mi++)
#pragma unroll
                for (int ni = 0; ni < 4; ni++)
                    MMAF16(d[mi][ni], fAh[mi], fBh[ni]);
            if (two) {
                uint32_t fAl[4][4];
#pragma unroll
                for (int mi = 0; mi < 4; mi++)
                    LDSM_X4(fAl[mi], sA_l + SWZ(a_base[mi] + kb));
#pragma unroll
                for (int mi = 0; mi < 4; mi++)
#pragma unroll
                    for (int ni = 0; ni < 4; ni++)
                        MMAF16(d[mi][ni], fAl[mi], fBh[ni]);
            }
        }
    }

    // ---- epilogue ----
    const int q = lane >> 2;
    const int cpair = (lane & 3) << 1;
#pragma unroll
    for (int ni = 0; ni < 4; ni++) {
        const int n = bn + wn * 32 + ni * 8 + cpair;
        const float2 bs = *(const float2*)(bias + n);
#pragma unroll
        for (int mi = 0; mi < 4; mi++) {
#pragma unroll
            for (int hh = 0; hh < 2; hh++) {
                const int m = bm + wm * 64 + mi * 16 + q + hh * 8;
                float2 v;
                v.x = d[mi][ni][hh * 2 + 0] + bs.x;
                v.y = d[mi][ni][hh * 2 + 1] + bs.y;
                if (mode == 1) {
                    const int cc = n >> 10, hd = (n >> 6) & 15, dd = n & 63;
                    const int bb = m >> 11, ss = m & 2047;
                    const float sc = (cc == 0) ? 0.125f : 1.0f;
                    const size_t off = ((size_t)(bb * HEADS + hd) * SEQ + ss) * DH + dd;
                    __half* dh = (cc == 0) ? g_q_h : (cc == 1) ? g_k_h : g_v_h;
                    *(uint32_t*)(dh + off) =
                        h2u(__float2half(v.x * sc), __float2half(v.y * sc));
                } else {
                    *(float2*)(C + (size_t)m * N + n) = v;
                }
            }
        }
    }
}

// ---------------------------------------------------------------------------
// Tensor-core flash attention, plain fp16 1-pass (fp32 accumulate):
//   QK^T = Q*K,  PV = P*V.
// 128 threads / 4 warps, 128 q-rows per CTA, 2 CTAs/SM. 64-key tiles,
// cp.async double-buffered (Kh 8K + Vh 8K = 16K/stage).
// smem: Qh 16K | 2 x 16K stages = 48K.
// ---------------------------------------------------------------------------
#define AT_SMEM (48 * 1024 + 1024)

__global__ __launch_bounds__(128, 2) void attn_mma()
{
    extern __shared__ char smraw[];
    const uint32_t base = (smem_u32(smraw) + 1023u) & ~1023u;
    const uint32_t sQh = base;
    const uint32_t sStage = base + 16384;  // + s*16384: Kh 0 | Vh 8K

    const int tid = threadIdx.x, lane = tid & 31, wid = tid >> 5;
    const int bh = blockIdx.y;
    const int q0 = blockIdx.x << 7;
    const size_t hbase = (size_t)bh * (SEQ * DH);

    // ---- prologue: cp.async key-tile 0 ----
    {
        const uint32_t st = sStage;
#pragma unroll
        for (int j = 0; j < 4; j++) {
            const int idx = tid + (j << 7);        // 0..511
            const int r = idx >> 3, c = idx & 7;
            const uint32_t so = SWZ((uint32_t)r * 128 + (uint32_t)c * 16);
            const size_t g = hbase + (size_t)r * DH + c * 8;
            CP16(st + so,        g_k_h + g);
            CP16(st + 8192 + so, g_v_h + g);
        }
        CPCOMMIT();
    }
    // stage Q (one-time)
    for (int i = tid; i < 1024; i += 128) {
        const int r = i >> 3, c = i & 7;
        const uint32_t so = SWZ((uint32_t)r * 128 + (uint32_t)c * 16);
        const size_t g = hbase + (size_t)(q0 + r) * DH + c * 8;
        uint4 v = *(const uint4*)(g_q_h + g);
        STS128(sQh + so, v);
    }
    __syncthreads();

    // Q fragments (persistent): 2 m-frags x 4 k-steps
    uint32_t qh[2][4][4];
#pragma unroll
    for (int mi = 0; mi < 2; mi++) {
        const uint32_t qoff =
            (uint32_t)(wid * 32 + mi * 16 + (lane & 15)) * 128 + ((lane >> 4) << 4);
#pragma unroll
        for (int ks = 0; ks < 4; ks++)
            LDSM_X4(qh[mi][ks], sQh + SWZ(qoff + ks * 32));
    }

    float O[2][8][4];
#pragma unroll
    for (int mi = 0; mi < 2; mi++)
#pragma unroll
        for (int nt = 0; nt < 8; nt++)
#pragma unroll
            for (int e = 0; e < 4; e++) O[mi][nt][e] = 0.f;
    float m_i[2][2], l_i[2][2];
#pragma unroll
    for (int mi = 0; mi < 2; mi++) {
        m_i[mi][0] = m_i[mi][1] = -3.0e38f;
        l_i[mi][0] = l_i[mi][1] = 0.f;
    }

    const int krow = (lane & 7) + ((lane >> 4) << 3);
    const uint32_t kchunk = (((uint32_t)lane >> 3) & 1) << 4;
    const int vrow_l = lane & 15;
    const uint32_t vchunk = ((uint32_t)lane >> 4) << 4;

    for (int kt = 0; kt < SEQ / 64; kt++) {
        CPWAIT0();
        __syncthreads();

        if (kt + 1 < SEQ / 64) {
            const size_t rb = hbase + (size_t)((kt + 1) << 6) * DH;
            const uint32_t st = sStage + ((kt + 1) & 1) * 16384;
#pragma unroll
            for (int j = 0; j < 4; j++) {
                const int idx = tid + (j << 7);
                const int r = idx >> 3, c = idx & 7;
                const uint32_t so = SWZ((uint32_t)r * 128 + (uint32_t)c * 16);
                const size_t g = rb + (size_t)r * DH + c * 8;
                CP16(st + so,        g_k_h + g);
                CP16(st + 8192 + so, g_v_h + g);
            }
            CPCOMMIT();
        }

        const uint32_t stK_h = sStage + (kt & 1) * 16384;
        const uint32_t stV_h = stK_h + 8192;

        // ---- S = Q @ K^T ----
        float S[2][8][4];
#pragma unroll
        for (int mi = 0; mi < 2; mi++)
#pragma unroll
            for (int nt = 0; nt < 8; nt++)
#pragma unroll
                for (int e = 0; e < 4; e++) S[mi][nt][e] = 0.f;

#pragma unroll
        for (int ks = 0; ks < 4; ks++) {
            uint32_t kbh[4][4];
#pragma unroll
            for (int g = 0; g < 4; g++) {
                const uint32_t off = SWZ((uint32_t)(g * 16 + krow) * 128 + (ks << 5) + kchunk);
                LDSM_X4(kbh[g], stK_h + off);
            }
#pragma unroll
            for (int g = 0; g < 4; g++)
#pragma unroll
                for (int mi = 0; mi < 2; mi++) {
                    MMAF16(S[mi][2 * g],     qh[mi][ks], &kbh[g][0]);
                    MMAF16(S[mi][2 * g + 1], qh[mi][ks], &kbh[g][2]);
                }
        }

        // ---- online softmax per m-frag ----
#pragma unroll
        for (int mi = 0; mi < 2; mi++) {
            float rx0 = -3.0e38f, rx1 = -3.0e38f;
#pragma unroll
            for (int nt = 0; nt < 8; nt++) {
                rx0 = fmaxf(rx0, fmaxf(S[mi][nt][0], S[mi][nt][1]));
                rx1 = fmaxf(rx1, fmaxf(S[mi][nt][2], S[mi][nt][3]));
            }
            rx0 = fmaxf(rx0, __shfl_xor_sync(0xffffffffu, rx0, 1));
            rx0 = fmaxf(rx0, __shfl_xor_sync(0xffffffffu, rx0, 2));
            rx1 = fmaxf(rx1, __shfl_xor_sync(0xffffffffu, rx1, 1));
            rx1 = fmaxf(rx1, __shfl_xor_sync(0xffffffffu, rx1, 2));
            const float mn0 = fmaxf(m_i[mi][0], rx0), mn1 = fmaxf(m_i[mi][1], rx1);
            const float a0 = __expf(m_i[mi][0] - mn0), a1 = __expf(m_i[mi][1] - mn1);
            float s0 = 0.f, s1 = 0.f;
#pragma unroll
            for (int nt = 0; nt < 8; nt++) {
                S[mi][nt][0] = __expf(S[mi][nt][0] - mn0);
                S[mi][nt][1] = __expf(S[mi][nt][1] - mn0);
                S[mi][nt][2] = __expf(S[mi][nt][2] - mn1);
                S[mi][nt][3] = __expf(S[mi][nt][3] - mn1);
                s0 += S[mi][nt][0] + S[mi][nt][1];
                s1 += S[mi][nt][2] + S[mi][nt][3];
            }
            s0 += __shfl_xor_sync(0xffffffffu, s0, 1);
            s0 += __shfl_xor_sync(0xffffffffu, s0, 2);
            s1 += __shfl_xor_sync(0xffffffffu, s1, 1);
            s1 += __shfl_xor_sync(0xffffffffu, s1, 2);
            l_i[mi][0] = l_i[mi][0] * a0 + s0;
            l_i[mi][1] = l_i[mi][1] * a1 + s1;
            m_i[mi][0] = mn0; m_i[mi][1] = mn1;
#pragma unroll
            for (int nt = 0; nt < 8; nt++) {
                O[mi][nt][0] *= a0; O[mi][nt][1] *= a0;
                O[mi][nt][2] *= a1; O[mi][nt][3] *= a1;
            }
        }

        // ---- PV: O += P @ V  (V^T via ldmatrix.trans) ----
#pragma unroll
        for (int c = 0; c < 4; c++) {
            uint32_t ph[2][4];
#pragma unroll
            for (int mi = 0; mi < 2; mi++)
#pragma unroll
                for (int j = 0; j < 4; j++) {
                    const int nt = 2 * c + (j >> 1);
                    const int e0 = (j & 1) * 2;
                    ph[mi][j] = h2u(__float2half(S[mi][nt][e0]),
                                    __float2half(S[mi][nt][e0 + 1]));
                }
#pragma unroll
            for (int g = 0; g < 4; g++) {
                uint32_t vbh[4];
                const uint32_t off =
                    SWZ((uint32_t)(c * 16 + vrow_l) * 128 + ((uint32_t)g << 5) + vchunk);
                LDSM_X4T(vbh, stV_h + off);
#pragma unroll
                for (int mi = 0; mi < 2; mi++) {
                    MMAF16(O[mi][2 * g],     ph[mi], &vbh[0]);
                    MMAF16(O[mi][2 * g + 1], ph[mi], &vbh[2]);
                }
            }
        }
    }

    // ---- finalize: O/l -> fp16 hi/lo -> g_attn [b][s][h*64+d] ----
    const int b_ = bh >> 4, h_ = bh & 15;
#pragma unroll
    for (int mi = 0; mi < 2; mi++) {
        const float inv0 = 1.0f / l_i[mi][0], inv1 = 1.0f / l_i[mi][1];
        const int row0 = q0 + wid * 32 + mi * 16 + (lane >> 2);
#pragma unroll
        for (int nt = 0; nt < 8; nt++) {
            const int dcol = nt * 8 + ((lane & 3) << 1);
#pragma unroll
            for (int hh = 0; hh < 2; hh++) {
                const int row = row0 + hh * 8;
                const float inv = hh ? inv1 : inv0;
                const float v0 = O[mi][nt][hh * 2 + 0] * inv;
                const float v1 = O[mi][nt][hh * 2 + 1] * inv;
                const __half h0 = __float2half(v0);
                const __half h1 = __float2half(v1);
                const size_t off = ((size_t)b_ * SEQ + row) * HID + h_ * DH + dcol;
                *(uint32_t*)(g_attn_h + off) = h2u(h0, h1);
                *(uint32_t*)(g_attn_l + off) =
                    h2u(__float2half(v0 - __half2float(h0)),
                        __float2half(v1 - __half2float(h1)));
            }
        }
    }
}

// ---------------------------------------------------------------------------
extern "C" void kernel_launch(void* const* d_in, const int* in_sizes, int n_in,
                              void* d_out, int out_size)
{
    const float* x    = (const float*)d_in[0];
    const float* Wqkv = (const float*)d_in[1];
    const float* bqkv = (const float*)d_in[2];
    const float* Wout = (const float*)d_in[3];
    const float* bout = (const float*)d_in[4];
    float* out = (float*)d_out;

    cudaFuncSetAttribute(gemm_tc,
                         cudaFuncAttributeMaxDynamicSharedMemorySize, GT_SMEM);
    cudaFuncSetAttribute(attn_mma,
                         cudaFuncAttributeMaxDynamicSharedMemorySize, AT_SMEM);

    __half *xh, *wqh, *woh, *ath, *atl;
    cudaGetSymbolAddress((void**)&xh,  g_x_h);
    cudaGetSymbolAddress((void**)&wqh, g_wq_h);
    cudaGetSymbolAddress((void**)&woh, g_wo_h);
    cudaGetSymbolAddress((void**)&ath, g_attn_h);
    cudaGetSymbolAddress((void**)&atl, g_attn_l);

    // 0) prep: cast x to fp16; transpose weights to fp16
    cast_f16<<<(MTOT * HID / 4 + 255) / 256, 256>>>(x, xh, MTOT * HID / 4);
    transpose_h<<<dim3(3 * HID / 32, HID / 32), dim3(32, 8)>>>(Wqkv, wqh, HID, 3 * HID);
    transpose_h<<<dim3(HID / 32, HID / 32), dim3(32, 8)>>>(Wout, woh, HID, HID);

    // 1) QKV projection (fp16 1-pass) -> Q/K/V fp16 (Q pre-scaled by 1/8)
    gemm_tc<<<dim3(3 * HID / 128, MTOT / 128), 256, GT_SMEM>>>(
        xh, nullptr, wqh, bqkv, nullptr, MTOT, 3 * HID, HID, 1);

    // 2) Tensor-core flash attention (fp16 1-pass) -> g_attn fp16 hi/lo
    attn_mma<<<dim3(SEQ / 128, NBH), 128, AT_SMEM>>>();

    // 3) Output projection (fp16 2-pass: attn 22-bit) + bias -> out
    gemm_tc<<<dim3(HID / 128, MTOT / 128), 256, GT_SMEM>>>(
        ath, atl, woh, bout, out, MTOT, HID, HID, 0);
}